// round 3
// baseline (speedup 1.0000x reference)
#include <cuda_runtime.h>
#include <math.h>

#define Dm 2048
#define Hn 16
#define Dh 128
#define Bb 2
#define Ll 2048
#define Mm (Bb*Ll)   /* 4096 rows */

// ---------------- scratch (static device globals; no runtime allocation) ----
__device__ float g_Q[(size_t)Mm * Dm];
__device__ float g_K[(size_t)Mm * Dm];
__device__ float g_V[(size_t)Mm * Dm];
__device__ float g_O[(size_t)Mm * Dm];
__device__ float g_invf[Dh/2];

// ---------------- inv_freq table (64 threads, double pow for exactness) -----
__global__ void invf_kernel() {
    int i = threadIdx.x;
    if (i < Dh/2)
        g_invf[i] = (float)pow(10000.0, -(double)(2*i) / (double)Dh);
}

// ---------------- SGEMM: C[M,N] = A[M,K] * W[N,K]^T  (NT, fp32) -------------
// BM=BN=128, BK=8, 256 threads, 8x8 micro-tile, register prefetch.
__global__ void __launch_bounds__(256, 2)
sgemm_nt(const float* __restrict__ A, const float* __restrict__ W,
         float* __restrict__ C, int Kdim, int Ndim)
{
    __shared__ float As[8][128];
    __shared__ float Bs[8][128];
    const int tid = threadIdx.x;
    const int tx = tid & 15, ty = tid >> 4;
    const int row0 = blockIdx.y << 7;
    const int col0 = blockIdx.x << 7;

    const int lr = tid >> 1;          // 0..127
    const int lk = (tid & 1) << 2;    // 0 or 4
    const float* Ap = A + (size_t)(row0 + lr) * Kdim + lk;
    const float* Wp = W + (size_t)(col0 + lr) * Kdim + lk;

    float acc[8][8];
#pragma unroll
    for (int i = 0; i < 8; i++)
#pragma unroll
        for (int j = 0; j < 8; j++) acc[i][j] = 0.f;

    float4 a4 = *(const float4*)Ap;
    float4 b4 = *(const float4*)Wp;

    for (int k0 = 0; k0 < Kdim; k0 += 8) {
        As[lk+0][lr] = a4.x; As[lk+1][lr] = a4.y; As[lk+2][lr] = a4.z; As[lk+3][lr] = a4.w;
        Bs[lk+0][lr] = b4.x; Bs[lk+1][lr] = b4.y; Bs[lk+2][lr] = b4.z; Bs[lk+3][lr] = b4.w;
        __syncthreads();
        if (k0 + 8 < Kdim) {
            a4 = *(const float4*)(Ap + k0 + 8);
            b4 = *(const float4*)(Wp + k0 + 8);
        }
#pragma unroll
        for (int kk = 0; kk < 8; kk++) {
            float ar[8], br[8];
            *(float4*)&ar[0] = *(const float4*)&As[kk][ty*8];
            *(float4*)&ar[4] = *(const float4*)&As[kk][ty*8+4];
            *(float4*)&br[0] = *(const float4*)&Bs[kk][tx*8];
            *(float4*)&br[4] = *(const float4*)&Bs[kk][tx*8+4];
#pragma unroll
            for (int i = 0; i < 8; i++)
#pragma unroll
                for (int j = 0; j < 8; j++)
                    acc[i][j] = fmaf(ar[i], br[j], acc[i][j]);
        }
        __syncthreads();
    }

#pragma unroll
    for (int i = 0; i < 8; i++) {
        float* cp = C + (size_t)(row0 + ty*8 + i) * Ndim + col0 + tx*8;
        *(float4*)cp     = make_float4(acc[i][0], acc[i][1], acc[i][2], acc[i][3]);
        *(float4*)(cp+4) = make_float4(acc[i][4], acc[i][5], acc[i][6], acc[i][7]);
    }
}

// ---------------- RoPE (in-place on Q and K) ---------------------------------
__global__ void rope_kernel(const int* __restrict__ pos,
                            float* __restrict__ Q, float* __restrict__ K)
{
    int idx = blockIdx.x * blockDim.x + threadIdx.x;    // over B*L*H*(Dh/2) = 2^22
    int i = idx & 63;
    int h = (idx >> 6) & 15;
    int l = (idx >> 10) & (Ll - 1);
    int b = idx >> 21;

    int p = pos[b * Ll + l];
    float ph = (float)p * g_invf[i];
    float s, c;
    sincosf(ph, &s, &c);

    size_t base = ((size_t)(b * Ll + l)) * Dm + h * Dh + 2 * i;
    float q1 = Q[base], q2 = Q[base + 1];
    Q[base]     = q1 * c - q2 * s;
    Q[base + 1] = q1 * s + q2 * c;
    float k1 = K[base], k2 = K[base + 1];
    K[base]     = k1 * c - k2 * s;
    K[base + 1] = k1 * s + k2 * c;
}

// ---------------- fused causal flash attention (fp32) ------------------------
// Block = (b, h, q-tile of 64 rows). 256 threads. dh=128 fully in shared.
// Q,K tiles stored k-major [128][64] with XOR swizzle -> conflict-free float4
// loads in the S-GEMM hot loop. V row-major [64][128]. S in [64][68].
#define ATT_SMEM_FLOATS (8192*3 + 64*68 + 192)

__global__ void __launch_bounds__(256, 1)
attn_kernel(const float* __restrict__ Q, const float* __restrict__ Kg,
            const float* __restrict__ V, float* __restrict__ O)
{
    extern __shared__ float sm[];
    float* Qt  = sm;             // [128][64] swizzled, k-major
    float* Kt  = sm + 8192;
    float* Vs  = sm + 16384;     // [64][128]
    float* Ss  = sm + 24576;     // [64][68]
    float* m_s = Ss + 64*68;
    float* l_s = m_s + 64;
    float* a_s = l_s + 64;

    const int tid  = threadIdx.x;
    const int lane = tid & 31, wid = tid >> 5;
    const int tx = tid & 15, ty = tid >> 4;
    const int qt = (int)(gridDim.x - 1 - blockIdx.x);  // heavy tiles first
    const int h  = blockIdx.y, b = blockIdx.z;
    const int qi0 = qt * 64;
    const size_t rowbase = (size_t)b * Ll;
    const int hoff = h * Dh;
    const float NEG = -1e30f;
    const float SCALE = 0.08838834764831845f;  // 1/sqrt(128)

    // load Q tile -> Qt (transposed + swizzled)
#pragma unroll
    for (int it = 0; it < 8; it++) {
        int r  = wid + 8 * it;
        int kq = lane << 2;
        float4 v = *(const float4*)(Q + (rowbase + qi0 + r) * Dm + hoff + kq);
        int g = r >> 2, rb = r & 3;
        const float* vp = (const float*)&v;
#pragma unroll
        for (int c = 0; c < 4; c++) {
            int k = kq + c;
            Qt[k*64 + (((g ^ (k >> 2)) & 15) << 2) + rb] = vp[c];
        }
    }
    if (tid < 64) { m_s[tid] = __int_as_float(0xff800000); l_s[tid] = 0.f; }

    float oacc[4][8];
#pragma unroll
    for (int i = 0; i < 4; i++)
#pragma unroll
        for (int j = 0; j < 8; j++) oacc[i][j] = 0.f;

    for (int kt = 0; kt <= qt; kt++) {
        const int kj0 = kt * 64;
        __syncthreads();
        // load K (swizzled k-major) and V (row-major)
#pragma unroll
        for (int it = 0; it < 8; it++) {
            int r  = wid + 8 * it;
            int kq = lane << 2;
            float4 kv = *(const float4*)(Kg + (rowbase + kj0 + r) * Dm + hoff + kq);
            int g = r >> 2, rb = r & 3;
            const float* kp = (const float*)&kv;
#pragma unroll
            for (int c = 0; c < 4; c++) {
                int k = kq + c;
                Kt[k*64 + (((g ^ (k >> 2)) & 15) << 2) + rb] = kp[c];
            }
            float4 vv = *(const float4*)(V + (rowbase + kj0 + r) * Dm + hoff + kq);
            *(float4*)&Vs[r*128 + kq] = vv;
        }
        __syncthreads();

        // S = Q K^T  (4x4 micro-tile per thread)
        float sacc[4][4];
#pragma unroll
        for (int i = 0; i < 4; i++)
#pragma unroll
            for (int j = 0; j < 4; j++) sacc[i][j] = 0.f;

#pragma unroll 8
        for (int k = 0; k < 128; k++) {
            int sw = (k >> 2) & 15;
            float4 aq = *(const float4*)&Qt[k*64 + ((ty ^ sw) << 2)];
            float4 bk = *(const float4*)&Kt[k*64 + ((tx ^ sw) << 2)];
            const float* ap = (const float*)&aq;
            const float* bp = (const float*)&bk;
#pragma unroll
            for (int i = 0; i < 4; i++)
#pragma unroll
                for (int j = 0; j < 4; j++)
                    sacc[i][j] = fmaf(ap[i], bp[j], sacc[i][j]);
        }
        const bool diag = (kt == qt);
#pragma unroll
        for (int i = 0; i < 4; i++)
#pragma unroll
            for (int j = 0; j < 4; j++) {
                float v = sacc[i][j] * SCALE;
                if (diag && (tx*4 + j) > (ty*4 + i)) v = NEG;
                Ss[(ty*4 + i)*68 + tx*4 + j] = v;
            }
        __syncthreads();

        // online softmax (4 threads per row)
        {
            int r = tid >> 2, sg = tid & 3;
            float* row = Ss + r*68 + sg*16;
            float mo = m_s[r];
            float mx = NEG;
#pragma unroll
            for (int c = 0; c < 16; c++) mx = fmaxf(mx, row[c]);
            mx = fmaxf(mx, __shfl_xor_sync(0xffffffffu, mx, 1));
            mx = fmaxf(mx, __shfl_xor_sync(0xffffffffu, mx, 2));
            float mn = fmaxf(mo, mx);
            float alpha = expf(mo - mn);
            float sum = 0.f;
#pragma unroll
            for (int c = 0; c < 16; c++) {
                float p = expf(row[c] - mn);
                row[c] = p;
                sum += p;
            }
            sum += __shfl_xor_sync(0xffffffffu, sum, 1);
            sum += __shfl_xor_sync(0xffffffffu, sum, 2);
            if (sg == 0) {
                m_s[r] = mn;
                l_s[r] = l_s[r] * alpha + sum;
                a_s[r] = alpha;
            }
        }
        __syncthreads();

        // rescale O, accumulate P*V
#pragma unroll
        for (int i = 0; i < 4; i++) {
            float al = a_s[ty*4 + i];
#pragma unroll
            for (int j = 0; j < 8; j++) oacc[i][j] *= al;
        }
#pragma unroll 4
        for (int j = 0; j < 64; j++) {
            float p0 = Ss[(ty*4 + 0)*68 + j];
            float p1 = Ss[(ty*4 + 1)*68 + j];
            float p2 = Ss[(ty*4 + 2)*68 + j];
            float p3 = Ss[(ty*4 + 3)*68 + j];
            float4 v0 = *(const float4*)&Vs[j*128 + tx*8];
            float4 v1 = *(const float4*)&Vs[j*128 + tx*8 + 4];
            const float* va = (const float*)&v0;
            const float* vb = (const float*)&v1;
#pragma unroll
            for (int c = 0; c < 4; c++) {
                oacc[0][c]   = fmaf(p0, va[c], oacc[0][c]);
                oacc[1][c]   = fmaf(p1, va[c], oacc[1][c]);
                oacc[2][c]   = fmaf(p2, va[c], oacc[2][c]);
                oacc[3][c]   = fmaf(p3, va[c], oacc[3][c]);
                oacc[0][4+c] = fmaf(p0, vb[c], oacc[0][4+c]);
                oacc[1][4+c] = fmaf(p1, vb[c], oacc[1][4+c]);
                oacc[2][4+c] = fmaf(p2, vb[c], oacc[2][4+c]);
                oacc[3][4+c] = fmaf(p3, vb[c], oacc[3][4+c]);
            }
        }
    }

    // epilogue: O / l, write
#pragma unroll
    for (int i = 0; i < 4; i++) {
        float inv = 1.f / l_s[ty*4 + i];
        float* op = O + (rowbase + qi0 + ty*4 + i) * Dm + hoff + tx*8;
        *(float4*)op     = make_float4(oacc[i][0]*inv, oacc[i][1]*inv,
                                       oacc[i][2]*inv, oacc[i][3]*inv);
        *(float4*)(op+4) = make_float4(oacc[i][4]*inv, oacc[i][5]*inv,
                                       oacc[i][6]*inv, oacc[i][7]*inv);
    }
}

// ---------------- launch ------------------------------------------------------
extern "C" void kernel_launch(void* const* d_in, const int* in_sizes, int n_in,
                              void* d_out, int out_size)
{
    const float* x  = (const float*)d_in[0];
    const int*  pos = (const int*)d_in[1];
    const float* Wq = (const float*)d_in[2];
    const float* Wk = (const float*)d_in[3];
    const float* Wv = (const float*)d_in[4];
    const float* Wo = (const float*)d_in[5];
    float* out = (float*)d_out;

    float *qp, *kp, *vp, *op;
    cudaGetSymbolAddress((void**)&qp, g_Q);
    cudaGetSymbolAddress((void**)&kp, g_K);
    cudaGetSymbolAddress((void**)&vp, g_V);
    cudaGetSymbolAddress((void**)&op, g_O);

    invf_kernel<<<1, 64>>>();

    dim3 gblk(Dm/128, Mm/128);   // (16, 32)
    sgemm_nt<<<gblk, 256>>>(x, Wq, qp, Dm, Dm);
    sgemm_nt<<<gblk, 256>>>(x, Wk, kp, Dm, Dm);
    sgemm_nt<<<gblk, 256>>>(x, Wv, vp, Dm, Dm);

    int npairs = Bb * Ll * Hn * (Dh/2);
    rope_kernel<<<npairs/256, 256>>>(pos, qp, kp);

    cudaFuncSetAttribute(attn_kernel,
                         cudaFuncAttributeMaxDynamicSharedMemorySize,
                         ATT_SMEM_FLOATS * (int)sizeof(float));
    dim3 agrid(Ll/64, Hn, Bb);
    attn_kernel<<<agrid, 256, ATT_SMEM_FLOATS * (int)sizeof(float)>>>(qp, kp, vp, op);

    sgemm_nt<<<gblk, 256>>>(op, Wo, out, Dm, Dm);
}

// round 5
// speedup vs baseline: 3.2399x; 3.2399x over previous
#include <cuda_runtime.h>
#include <cuda_bf16.h>
#include <math.h>
#include <stdint.h>

#define Dm 2048
#define Hn 16
#define Dh 128
#define Bb 2
#define Ll 2048
#define Mm (Bb*Ll)   /* 4096 rows */

// ---------------- scratch (static device globals; no runtime allocation) ----
__device__ float g_Q[(size_t)Mm * Dm];
__device__ float g_K[(size_t)Mm * Dm];
__device__ float g_V[(size_t)Mm * Dm];
__device__ float g_O[(size_t)Mm * Dm];
__device__ __nv_bfloat16 g_ahi[(size_t)Mm * Dm];   // activation hi
__device__ __nv_bfloat16 g_alo[(size_t)Mm * Dm];   // activation lo
__device__ __nv_bfloat16 g_whi[(size_t)Dm * Dm];   // current weight hi
__device__ __nv_bfloat16 g_wlo[(size_t)Dm * Dm];   // current weight lo
__device__ float g_invf[Dh/2];

// ======================= helpers =============================================
__device__ __forceinline__ uint32_t smem_u32(const void* p) {
    uint32_t a;
    asm("{ .reg .u64 t; cvta.to.shared.u64 t, %1; cvt.u32.u64 %0, t; }"
        : "=r"(a) : "l"(p));
    return a;
}
__device__ __forceinline__ void cp_async16(uint32_t saddr, const void* gaddr) {
    asm volatile("cp.async.cg.shared.global [%0], [%1], 16;"
                 :: "r"(saddr), "l"(gaddr) : "memory");
}
#define CP_COMMIT() asm volatile("cp.async.commit_group;" ::: "memory")
#define CP_WAIT1()  asm volatile("cp.async.wait_group 1;" ::: "memory")
#define CP_WAIT0()  asm volatile("cp.async.wait_group 0;" ::: "memory")

__device__ __forceinline__ void ldsm4(uint32_t* d, uint32_t a) {
    asm volatile("ldmatrix.sync.aligned.m8n8.x4.shared.b16 {%0,%1,%2,%3}, [%4];"
                 : "=r"(d[0]), "=r"(d[1]), "=r"(d[2]), "=r"(d[3]) : "r"(a));
}
__device__ __forceinline__ void mma16816(float* d, const uint32_t* a,
                                         uint32_t b0, uint32_t b1) {
    asm volatile(
        "mma.sync.aligned.m16n8k16.row.col.f32.bf16.bf16.f32 "
        "{%0,%1,%2,%3}, {%4,%5,%6,%7}, {%8,%9}, {%0,%1,%2,%3};"
        : "+f"(d[0]), "+f"(d[1]), "+f"(d[2]), "+f"(d[3])
        : "r"(a[0]), "r"(a[1]), "r"(a[2]), "r"(a[3]), "r"(b0), "r"(b1));
}

// ---------------- inv_freq table --------------------------------------------
__global__ void invf_kernel() {
    int i = threadIdx.x;
    if (i < Dh/2)
        g_invf[i] = (float)pow(10000.0, -(double)(2*i) / (double)Dh);
}

// ---------------- fp32 -> bf16 hi/lo split -----------------------------------
__global__ void split_bf16(const float4* __restrict__ src,
                           __nv_bfloat162* __restrict__ hi,
                           __nv_bfloat162* __restrict__ lo, int n4)
{
    int i = blockIdx.x * blockDim.x + threadIdx.x;
    if (i >= n4) return;
    float4 v = src[i];
    __nv_bfloat16 hx = __float2bfloat16(v.x);
    __nv_bfloat16 hy = __float2bfloat16(v.y);
    __nv_bfloat16 hz = __float2bfloat16(v.z);
    __nv_bfloat16 hw = __float2bfloat16(v.w);
    __nv_bfloat16 lx = __float2bfloat16(v.x - __bfloat162float(hx));
    __nv_bfloat16 ly = __float2bfloat16(v.y - __bfloat162float(hy));
    __nv_bfloat16 lz = __float2bfloat16(v.z - __bfloat162float(hz));
    __nv_bfloat16 lw = __float2bfloat16(v.w - __bfloat162float(hw));
    hi[2*i]   = __halves2bfloat162(hx, hy);
    hi[2*i+1] = __halves2bfloat162(hz, hw);
    lo[2*i]   = __halves2bfloat162(lx, ly);
    lo[2*i+1] = __halves2bfloat162(lz, lw);
}

// ---------------- bf16x3 GEMM via mma.sync: C[M,N] = A[M,K] * W[N,K]^T -------
// 128x128 CTA tile, K-chunk 64 bf16 (128B rows, SW128 XOR swizzle),
// cp.async double buffer, 8 warps x (64x32) m16n8k16 micro-tiles, fp32 acc.
#define KC 64
#define TILE_B 16384           /* 128 rows x 128B */
#define STAGE_B (4*TILE_B)     /* Ahi, Alo, Bhi, Blo */
#define GEMM_SMEM (1024 + 2*STAGE_B)

__global__ void __launch_bounds__(256, 1)
gemm_bf16x3(const __nv_bfloat16* __restrict__ Ahi, const __nv_bfloat16* __restrict__ Alo,
            const __nv_bfloat16* __restrict__ Bhi, const __nv_bfloat16* __restrict__ Blo,
            float* __restrict__ C, int Ko, int No)
{
    extern __shared__ char smraw[];
    char* smal = (char*)(((uintptr_t)smraw + 1023) & ~(uintptr_t)1023);
    const uint32_t su = smem_u32(smal);

    const int tid = threadIdx.x;
    const int lane = tid & 31, wid = tid >> 5;
    const int row0 = blockIdx.y << 7;
    const int col0 = blockIdx.x << 7;
    const int wm = wid >> 2, wn = wid & 3;     // warp tile: rows wm*64, cols wn*32

    const char* srcs[4];
    srcs[0] = (const char*)(Ahi + (size_t)row0 * Ko);
    srcs[1] = (const char*)(Alo + (size_t)row0 * Ko);
    srcs[2] = (const char*)(Bhi + (size_t)col0 * Ko);
    srcs[3] = (const char*)(Blo + (size_t)col0 * Ko);
    const size_t rstride = (size_t)Ko * 2;

    // per-thread loader coords (16B units): 1024 units per tile, 4 iters x 256 thr
    // unit u: row r = u>>3, 16B col cb = (u&7)*16; SW128: cb ^= (r&7)<<4
    // fragment address bases
    uint32_t aoff[4], ar7[4];
#pragma unroll
    for (int m = 0; m < 4; m++) {
        int r = wm*64 + m*16 + (lane & 15);
        aoff[m] = ((r >> 3) << 10) + ((r & 7) << 7);
        ar7[m]  = r & 7;
    }
    uint32_t boff[4], br7[4];
#pragma unroll
    for (int n = 0; n < 4; n++) {
        int r = wn*32 + n*8 + (lane & 7);
        boff[n] = ((r >> 3) << 10) + ((r & 7) << 7);
        br7[n]  = r & 7;
    }
    const uint32_t uA_lo = lane >> 4;   // 0..1
    const uint32_t uB_lo = lane >> 3;   // 0..3

    float acc[4][4][4];
#pragma unroll
    for (int m = 0; m < 4; m++)
#pragma unroll
        for (int n = 0; n < 4; n++)
#pragma unroll
            for (int q = 0; q < 4; q++) acc[m][n][q] = 0.f;

    const int NCH = Ko / KC;            // 32

    // ---- issue chunk 0
    {
        uint32_t sbase = su;
#pragma unroll
        for (int t = 0; t < 4; t++) {
            const char* g = srcs[t];
            uint32_t s = sbase + t * TILE_B;
#pragma unroll
            for (int i = 0; i < 4; i++) {
                int u = tid + (i << 8);
                int r = u >> 3;
                int cb = (u & 7) << 4;
                uint32_t off = ((r >> 3) << 10) + ((r & 7) << 7) + (cb ^ ((r & 7) << 4));
                cp_async16(s + off, g + (size_t)r * rstride + cb);
            }
        }
        CP_COMMIT();
    }

    for (int c = 0; c < NCH; c++) {
        if (c + 1 < NCH) {
            uint32_t sbase = su + ((c + 1) & 1) * STAGE_B;
            const size_t kb = (size_t)(c + 1) * (KC * 2);
#pragma unroll
            for (int t = 0; t < 4; t++) {
                const char* g = srcs[t] + kb;
                uint32_t s = sbase + t * TILE_B;
#pragma unroll
                for (int i = 0; i < 4; i++) {
                    int u = tid + (i << 8);
                    int r = u >> 3;
                    int cb = (u & 7) << 4;
                    uint32_t off = ((r >> 3) << 10) + ((r & 7) << 7) + (cb ^ ((r & 7) << 4));
                    cp_async16(s + off, g + (size_t)r * rstride + cb);
                }
            }
            CP_COMMIT();
            CP_WAIT1();
        } else {
            CP_WAIT0();
        }
        __syncthreads();

        // ---- compute chunk c
        const uint32_t st  = su + (c & 1) * STAGE_B;
        const uint32_t SAh = st;
        const uint32_t SAl = st + TILE_B;
        const uint32_t SBh = st + 2 * TILE_B;
        const uint32_t SBl = st + 3 * TILE_B;

#pragma unroll
        for (int kp = 0; kp < 2; kp++) {
            uint32_t bh[4][4], bl[4][4];
#pragma unroll
            for (int n = 0; n < 4; n++) {
                uint32_t uB = 4*kp + uB_lo;
                uint32_t o = boff[n] + ((uB ^ br7[n]) << 4);
                ldsm4(bh[n], SBh + o);
                ldsm4(bl[n], SBl + o);
            }
#pragma unroll
            for (int ki = 0; ki < 2; ki++) {
                uint32_t uA = 2*(2*kp + ki) + uA_lo;
                uint32_t a[4][4];
#pragma unroll
                for (int m = 0; m < 4; m++)
                    ldsm4(a[m], SAh + aoff[m] + ((uA ^ ar7[m]) << 4));
#pragma unroll
                for (int m = 0; m < 4; m++)
#pragma unroll
                    for (int n = 0; n < 4; n++) {
                        mma16816(acc[m][n], a[m], bh[n][2*ki], bh[n][2*ki+1]);
                        mma16816(acc[m][n], a[m], bl[n][2*ki], bl[n][2*ki+1]);
                    }
#pragma unroll
                for (int m = 0; m < 4; m++)
                    ldsm4(a[m], SAl + aoff[m] + ((uA ^ ar7[m]) << 4));
#pragma unroll
                for (int m = 0; m < 4; m++)
#pragma unroll
                    for (int n = 0; n < 4; n++)
                        mma16816(acc[m][n], a[m], bh[n][2*ki], bh[n][2*ki+1]);
            }
        }
        __syncthreads();
    }

    // ---- epilogue: d-fragment layout -> fp32 C
#pragma unroll
    for (int m = 0; m < 4; m++) {
        int rw = row0 + wm*64 + m*16 + (lane >> 2);
#pragma unroll
        for (int n = 0; n < 4; n++) {
            int cw = col0 + wn*32 + n*8 + ((lane & 3) << 1);
            *(float2*)(C + (size_t)rw * No + cw) =
                make_float2(acc[m][n][0], acc[m][n][1]);
            *(float2*)(C + (size_t)(rw + 8) * No + cw) =
                make_float2(acc[m][n][2], acc[m][n][3]);
        }
    }
}

// ---------------- RoPE (in-place on Q and K) ---------------------------------
__global__ void rope_kernel(const int* __restrict__ pos,
                            float* __restrict__ Q, float* __restrict__ K)
{
    int idx = blockIdx.x * blockDim.x + threadIdx.x;
    int i = idx & 63;
    int h = (idx >> 6) & 15;
    int l = (idx >> 10) & (Ll - 1);
    int b = idx >> 21;

    int p = pos[b * Ll + l];
    float ph = (float)p * g_invf[i];
    float s, c;
    sincosf(ph, &s, &c);

    size_t base = ((size_t)(b * Ll + l)) * Dm + h * Dh + 2 * i;
    float q1 = Q[base], q2 = Q[base + 1];
    Q[base]     = q1 * c - q2 * s;
    Q[base + 1] = q1 * s + q2 * c;
    float k1 = K[base], k2 = K[base + 1];
    K[base]     = k1 * c - k2 * s;
    K[base + 1] = k1 * s + k2 * c;
}

// ---------------- fused causal flash attention (fp32) ------------------------
#define ATT_SMEM_FLOATS (8192*3 + 64*68 + 192)

__global__ void __launch_bounds__(256, 1)
attn_kernel(const float* __restrict__ Q, const float* __restrict__ Kg,
            const float* __restrict__ V, float* __restrict__ O)
{
    extern __shared__ float sm[];
    float* Qt  = sm;             // [128][64] swizzled, k-major
    float* Kt  = sm + 8192;
    float* Vs  = sm + 16384;     // [64][128]
    float* Ss  = sm + 24576;     // [64][68]
    float* m_s = Ss + 64*68;
    float* l_s = m_s + 64;
    float* a_s = l_s + 64;

    const int tid  = threadIdx.x;
    const int lane = tid & 31, wid = tid >> 5;
    const int tx = tid & 15, ty = tid >> 4;
    const int qt = (int)(gridDim.x - 1 - blockIdx.x);
    const int h  = blockIdx.y, b = blockIdx.z;
    const int qi0 = qt * 64;
    const size_t rowbase = (size_t)b * Ll;
    const int hoff = h * Dh;
    const float NEG = -1e30f;
    const float SCALE = 0.08838834764831845f;

#pragma unroll
    for (int it = 0; it < 8; it++) {
        int r  = wid + 8 * it;
        int kq = lane << 2;
        float4 v = *(const float4*)(Q + (rowbase + qi0 + r) * Dm + hoff + kq);
        int g = r >> 2, rb = r & 3;
        const float* vp = (const float*)&v;
#pragma unroll
        for (int c = 0; c < 4; c++) {
            int k = kq + c;
            Qt[k*64 + (((g ^ (k >> 2)) & 15) << 2) + rb] = vp[c];
        }
    }
    if (tid < 64) { m_s[tid] = __int_as_float(0xff800000); l_s[tid] = 0.f; }

    float oacc[4][8];
#pragma unroll
    for (int i = 0; i < 4; i++)
#pragma unroll
        for (int j = 0; j < 8; j++) oacc[i][j] = 0.f;

    for (int kt = 0; kt <= qt; kt++) {
        const int kj0 = kt * 64;
        __syncthreads();
#pragma unroll
        for (int it = 0; it < 8; it++) {
            int r  = wid + 8 * it;
            int kq = lane << 2;
            float4 kv = *(const float4*)(Kg + (rowbase + kj0 + r) * Dm + hoff + kq);
            int g = r >> 2, rb = r & 3;
            const float* kp = (const float*)&kv;
#pragma unroll
            for (int c = 0; c < 4; c++) {
                int k = kq + c;
                Kt[k*64 + (((g ^ (k >> 2)) & 15) << 2) + rb] = kp[c];
            }
            float4 vv = *(const float4*)(V + (rowbase + kj0 + r) * Dm + hoff + kq);
            *(float4*)&Vs[r*128 + kq] = vv;
        }
        __syncthreads();

        float sacc[4][4];
#pragma unroll
        for (int i = 0; i < 4; i++)
#pragma unroll
            for (int j = 0; j < 4; j++) sacc[i][j] = 0.f;

#pragma unroll 8
        for (int k = 0; k < 128; k++) {
            int sw = (k >> 2) & 15;
            float4 aq = *(const float4*)&Qt[k*64 + ((ty ^ sw) << 2)];
            float4 bk = *(const float4*)&Kt[k*64 + ((tx ^ sw) << 2)];
            const float* ap = (const float*)&aq;
            const float* bp = (const float*)&bk;
#pragma unroll
            for (int i = 0; i < 4; i++)
#pragma unroll
                for (int j = 0; j < 4; j++)
                    sacc[i][j] = fmaf(ap[i], bp[j], sacc[i][j]);
        }
        const bool diag = (kt == qt);
#pragma unroll
        for (int i = 0; i < 4; i++)
#pragma unroll
            for (int j = 0; j < 4; j++) {
                float v = sacc[i][j] * SCALE;
                if (diag && (tx*4 + j) > (ty*4 + i)) v = NEG;
                Ss[(ty*4 + i)*68 + tx*4 + j] = v;
            }
        __syncthreads();

        {
            int r = tid >> 2, sg = tid & 3;
            float* row = Ss + r*68 + sg*16;
            float mo = m_s[r];
            float mx = NEG;
#pragma unroll
            for (int c = 0; c < 16; c++) mx = fmaxf(mx, row[c]);
            mx = fmaxf(mx, __shfl_xor_sync(0xffffffffu, mx, 1));
            mx = fmaxf(mx, __shfl_xor_sync(0xffffffffu, mx, 2));
            float mn = fmaxf(mo, mx);
            float alpha = __expf(mo - mn);
            float sum = 0.f;
#pragma unroll
            for (int c = 0; c < 16; c++) {
                float p = __expf(row[c] - mn);
                row[c] = p;
                sum += p;
            }
            sum += __shfl_xor_sync(0xffffffffu, sum, 1);
            sum += __shfl_xor_sync(0xffffffffu, sum, 2);
            if (sg == 0) {
                m_s[r] = mn;
                l_s[r] = l_s[r] * alpha + sum;
                a_s[r] = alpha;
            }
        }
        __syncthreads();

#pragma unroll
        for (int i = 0; i < 4; i++) {
            float al = a_s[ty*4 + i];
#pragma unroll
            for (int j = 0; j < 8; j++) oacc[i][j] *= al;
        }
#pragma unroll 4
        for (int j = 0; j < 64; j++) {
            float p0 = Ss[(ty*4 + 0)*68 + j];
            float p1 = Ss[(ty*4 + 1)*68 + j];
            float p2 = Ss[(ty*4 + 2)*68 + j];
            float p3 = Ss[(ty*4 + 3)*68 + j];
            float4 v0 = *(const float4*)&Vs[j*128 + tx*8];
            float4 v1 = *(const float4*)&Vs[j*128 + tx*8 + 4];
            const float* va = (const float*)&v0;
            const float* vb = (const float*)&v1;
#pragma unroll
            for (int c = 0; c < 4; c++) {
                oacc[0][c]   = fmaf(p0, va[c], oacc[0][c]);
                oacc[1][c]   = fmaf(p1, va[c], oacc[1][c]);
                oacc[2][c]   = fmaf(p2, va[c], oacc[2][c]);
                oacc[3][c]   = fmaf(p3, va[c], oacc[3][c]);
                oacc[0][4+c] = fmaf(p0, vb[c], oacc[0][4+c]);
                oacc[1][4+c] = fmaf(p1, vb[c], oacc[1][4+c]);
                oacc[2][4+c] = fmaf(p2, vb[c], oacc[2][4+c]);
                oacc[3][4+c] = fmaf(p3, vb[c], oacc[3][4+c]);
            }
        }
    }

#pragma unroll
    for (int i = 0; i < 4; i++) {
        float inv = 1.f / l_s[ty*4 + i];
        float* op = O + (rowbase + qi0 + ty*4 + i) * Dm + hoff + tx*8;
        *(float4*)op     = make_float4(oacc[i][0]*inv, oacc[i][1]*inv,
                                       oacc[i][2]*inv, oacc[i][3]*inv);
        *(float4*)(op+4) = make_float4(oacc[i][4]*inv, oacc[i][5]*inv,
                                       oacc[i][6]*inv, oacc[i][7]*inv);
    }
}

// ---------------- launch ------------------------------------------------------
extern "C" void kernel_launch(void* const* d_in, const int* in_sizes, int n_in,
                              void* d_out, int out_size)
{
    const float* x  = (const float*)d_in[0];
    const int*  pos = (const int*)d_in[1];
    const float* Wq = (const float*)d_in[2];
    const float* Wk = (const float*)d_in[3];
    const float* Wv = (const float*)d_in[4];
    const float* Wo = (const float*)d_in[5];
    float* out = (float*)d_out;

    float *qp, *kp, *vp, *op;
    __nv_bfloat16 *ahi, *alo, *whi, *wlo;
    cudaGetSymbolAddress((void**)&qp, g_Q);
    cudaGetSymbolAddress((void**)&kp, g_K);
    cudaGetSymbolAddress((void**)&vp, g_V);
    cudaGetSymbolAddress((void**)&op, g_O);
    cudaGetSymbolAddress((void**)&ahi, g_ahi);
    cudaGetSymbolAddress((void**)&alo, g_alo);
    cudaGetSymbolAddress((void**)&whi, g_whi);
    cudaGetSymbolAddress((void**)&wlo, g_wlo);

    invf_kernel<<<1, 64>>>();

    const int nx4 = (Mm * Dm) / 4;
    const int nw4 = (Dm * Dm) / 4;

    cudaFuncSetAttribute(gemm_bf16x3,
                         cudaFuncAttributeMaxDynamicSharedMemorySize, GEMM_SMEM);
    dim3 ggrid(Dm/128, Mm/128);         // (16, 32)

    // x -> bf16 hi/lo once
    split_bf16<<<nx4/256, 256>>>((const float4*)x,
                                 (__nv_bfloat162*)ahi, (__nv_bfloat162*)alo, nx4);

    // Q = x Wq^T
    split_bf16<<<nw4/256, 256>>>((const float4*)Wq,
                                 (__nv_bfloat162*)whi, (__nv_bfloat162*)wlo, nw4);
    gemm_bf16x3<<<ggrid, 256, GEMM_SMEM>>>(ahi, alo, whi, wlo, qp, Dm, Dm);
    // K = x Wk^T
    split_bf16<<<nw4/256, 256>>>((const float4*)Wk,
                                 (__nv_bfloat162*)whi, (__nv_bfloat162*)wlo, nw4);
    gemm_bf16x3<<<ggrid, 256, GEMM_SMEM>>>(ahi, alo, whi, wlo, kp, Dm, Dm);
    // V = x Wv^T
    split_bf16<<<nw4/256, 256>>>((const float4*)Wv,
                                 (__nv_bfloat162*)whi, (__nv_bfloat162*)wlo, nw4);
    gemm_bf16x3<<<ggrid, 256, GEMM_SMEM>>>(ahi, alo, whi, wlo, vp, Dm, Dm);

    int npairs = Bb * Ll * Hn * (Dh/2);
    rope_kernel<<<npairs/256, 256>>>(pos, qp, kp);

    cudaFuncSetAttribute(attn_kernel,
                         cudaFuncAttributeMaxDynamicSharedMemorySize,
                         ATT_SMEM_FLOATS * (int)sizeof(float));
    dim3 agrid(Ll/64, Hn, Bb);
    attn_kernel<<<agrid, 256, ATT_SMEM_FLOATS * (int)sizeof(float)>>>(qp, kp, vp, op);

    // out = attn_out Wo^T
    split_bf16<<<nx4/256, 256>>>((const float4*)op,
                                 (__nv_bfloat162*)ahi, (__nv_bfloat162*)alo, nx4);
    split_bf16<<<nw4/256, 256>>>((const float4*)Wo,
                                 (__nv_bfloat162*)whi, (__nv_bfloat162*)wlo, nw4);
    gemm_bf16x3<<<ggrid, 256, GEMM_SMEM>>>(ahi, alo, whi, wlo, out, Dm, Dm);
}

// round 6
// speedup vs baseline: 5.3286x; 1.6447x over previous
#include <cuda_runtime.h>
#include <cuda_bf16.h>
#include <math.h>
#include <stdint.h>

#define Dm 2048
#define Hn 16
#define Dh 128
#define Bb 2
#define Ll 2048
#define Mm (Bb*Ll)   /* 4096 rows */
#define SCALE_C 0.08838834764831845f   /* 1/sqrt(128) */

// ---------------- scratch (static device globals; no runtime allocation) ----
__device__ float g_Q[(size_t)Mm * Dm];
__device__ float g_K[(size_t)Mm * Dm];
__device__ __nv_bfloat16 g_ahi[(size_t)Mm * Dm];   // x split, later O split (hi)
__device__ __nv_bfloat16 g_alo[(size_t)Mm * Dm];
__device__ __nv_bfloat16 g_whi[(size_t)Dm * Dm];
__device__ __nv_bfloat16 g_wlo[(size_t)Dm * Dm];
__device__ __nv_bfloat16 g_qhi[(size_t)Mm * Dm];
__device__ __nv_bfloat16 g_qlo[(size_t)Mm * Dm];
__device__ __nv_bfloat16 g_khi[(size_t)Mm * Dm];
__device__ __nv_bfloat16 g_klo[(size_t)Mm * Dm];
__device__ __nv_bfloat16 g_vhi[(size_t)Mm * Dm];
__device__ __nv_bfloat16 g_vlo[(size_t)Mm * Dm];
__device__ float g_invf[Dh/2];

// ======================= helpers =============================================
__device__ __forceinline__ uint32_t smem_u32(const void* p) {
    uint32_t a;
    asm("{ .reg .u64 t; cvta.to.shared.u64 t, %1; cvt.u32.u64 %0, t; }"
        : "=r"(a) : "l"(p));
    return a;
}
__device__ __forceinline__ void cp_async16(uint32_t saddr, const void* gaddr) {
    asm volatile("cp.async.cg.shared.global [%0], [%1], 16;"
                 :: "r"(saddr), "l"(gaddr) : "memory");
}
#define CP_COMMIT() asm volatile("cp.async.commit_group;" ::: "memory")
#define CP_WAIT1()  asm volatile("cp.async.wait_group 1;" ::: "memory")
#define CP_WAIT0()  asm volatile("cp.async.wait_group 0;" ::: "memory")

__device__ __forceinline__ void ldsm4(uint32_t* d, uint32_t a) {
    asm volatile("ldmatrix.sync.aligned.m8n8.x4.shared.b16 {%0,%1,%2,%3}, [%4];"
                 : "=r"(d[0]), "=r"(d[1]), "=r"(d[2]), "=r"(d[3]) : "r"(a));
}
__device__ __forceinline__ void ldsm4t(uint32_t* d, uint32_t a) {
    asm volatile("ldmatrix.sync.aligned.m8n8.x4.trans.shared.b16 {%0,%1,%2,%3}, [%4];"
                 : "=r"(d[0]), "=r"(d[1]), "=r"(d[2]), "=r"(d[3]) : "r"(a));
}
__device__ __forceinline__ void mma16816(float* d, const uint32_t* a,
                                         uint32_t b0, uint32_t b1) {
    asm volatile(
        "mma.sync.aligned.m16n8k16.row.col.f32.bf16.bf16.f32 "
        "{%0,%1,%2,%3}, {%4,%5,%6,%7}, {%8,%9}, {%0,%1,%2,%3};"
        : "+f"(d[0]), "+f"(d[1]), "+f"(d[2]), "+f"(d[3])
        : "r"(a[0]), "r"(a[1]), "r"(a[2]), "r"(a[3]), "r"(b0), "r"(b1));
}
__device__ __forceinline__ uint32_t pack_hi2(float a, float b) {
    __nv_bfloat162 t = __floats2bfloat162_rn(a, b);
    return *reinterpret_cast<uint32_t*>(&t);
}
__device__ __forceinline__ uint32_t pack_lo2(float a, float b) {
    float ra = a - __bfloat162float(__float2bfloat16_rn(a));
    float rb = b - __bfloat162float(__float2bfloat16_rn(b));
    __nv_bfloat162 t = __floats2bfloat162_rn(ra, rb);
    return *reinterpret_cast<uint32_t*>(&t);
}

// ---------------- inv_freq table --------------------------------------------
__global__ void invf_kernel() {
    int i = threadIdx.x;
    if (i < Dh/2)
        g_invf[i] = (float)pow(10000.0, -(double)(2*i) / (double)Dh);
}

// ---------------- fp32 -> bf16 hi/lo split -----------------------------------
__global__ void split_bf16(const float4* __restrict__ src,
                           __nv_bfloat162* __restrict__ hi,
                           __nv_bfloat162* __restrict__ lo, int n4)
{
    int i = blockIdx.x * blockDim.x + threadIdx.x;
    if (i >= n4) return;
    float4 v = src[i];
    __nv_bfloat16 hx = __float2bfloat16(v.x);
    __nv_bfloat16 hy = __float2bfloat16(v.y);
    __nv_bfloat16 hz = __float2bfloat16(v.z);
    __nv_bfloat16 hw = __float2bfloat16(v.w);
    __nv_bfloat16 lx = __float2bfloat16(v.x - __bfloat162float(hx));
    __nv_bfloat16 ly = __float2bfloat16(v.y - __bfloat162float(hy));
    __nv_bfloat16 lz = __float2bfloat16(v.z - __bfloat162float(hz));
    __nv_bfloat16 lw = __float2bfloat16(v.w - __bfloat162float(hw));
    hi[2*i]   = __halves2bfloat162(hx, hy);
    hi[2*i+1] = __halves2bfloat162(hz, hw);
    lo[2*i]   = __halves2bfloat162(lx, ly);
    lo[2*i+1] = __halves2bfloat162(lz, lw);
}

// ---------------- bf16x3 GEMM via mma.sync: C[M,N] = A[M,K] * W[N,K]^T -------
#define KC 64
#define TILE_B 16384
#define STAGE_B (4*TILE_B)
#define GEMM_SMEM (1024 + 2*STAGE_B)

__global__ void __launch_bounds__(256, 1)
gemm_bf16x3(const __nv_bfloat16* __restrict__ Ahi, const __nv_bfloat16* __restrict__ Alo,
            const __nv_bfloat16* __restrict__ Bhi, const __nv_bfloat16* __restrict__ Blo,
            float* __restrict__ C,
            __nv_bfloat16* __restrict__ Chi, __nv_bfloat16* __restrict__ Clo,
            int Ko, int No)
{
    extern __shared__ char smraw[];
    char* smal = (char*)(((uintptr_t)smraw + 1023) & ~(uintptr_t)1023);
    const uint32_t su = smem_u32(smal);

    const int tid = threadIdx.x;
    const int lane = tid & 31, wid = tid >> 5;
    const int row0 = blockIdx.y << 7;
    const int col0 = blockIdx.x << 7;
    const int wm = wid >> 2, wn = wid & 3;

    const char* srcs[4];
    srcs[0] = (const char*)(Ahi + (size_t)row0 * Ko);
    srcs[1] = (const char*)(Alo + (size_t)row0 * Ko);
    srcs[2] = (const char*)(Bhi + (size_t)col0 * Ko);
    srcs[3] = (const char*)(Blo + (size_t)col0 * Ko);
    const size_t rstride = (size_t)Ko * 2;

    uint32_t aoff[4], ar7[4];
#pragma unroll
    for (int m = 0; m < 4; m++) {
        int r = wm*64 + m*16 + (lane & 15);
        aoff[m] = ((r >> 3) << 10) + ((r & 7) << 7);
        ar7[m]  = r & 7;
    }
    uint32_t boff[4], br7[4];
#pragma unroll
    for (int n = 0; n < 4; n++) {
        int r = wn*32 + n*8 + (lane & 7);
        boff[n] = ((r >> 3) << 10) + ((r & 7) << 7);
        br7[n]  = r & 7;
    }
    const uint32_t uA_lo = lane >> 4;
    const uint32_t uB_lo = lane >> 3;

    float acc[4][4][4];
#pragma unroll
    for (int m = 0; m < 4; m++)
#pragma unroll
        for (int n = 0; n < 4; n++)
#pragma unroll
            for (int q = 0; q < 4; q++) acc[m][n][q] = 0.f;

    const int NCH = Ko / KC;

    {
        uint32_t sbase = su;
#pragma unroll
        for (int t = 0; t < 4; t++) {
            const char* g = srcs[t];
            uint32_t s = sbase + t * TILE_B;
#pragma unroll
            for (int i = 0; i < 4; i++) {
                int u = tid + (i << 8);
                int r = u >> 3;
                int cb = (u & 7) << 4;
                uint32_t off = ((r >> 3) << 10) + ((r & 7) << 7) + (cb ^ ((r & 7) << 4));
                cp_async16(s + off, g + (size_t)r * rstride + cb);
            }
        }
        CP_COMMIT();
    }

    for (int c = 0; c < NCH; c++) {
        if (c + 1 < NCH) {
            uint32_t sbase = su + ((c + 1) & 1) * STAGE_B;
            const size_t kb = (size_t)(c + 1) * (KC * 2);
#pragma unroll
            for (int t = 0; t < 4; t++) {
                const char* g = srcs[t] + kb;
                uint32_t s = sbase + t * TILE_B;
#pragma unroll
                for (int i = 0; i < 4; i++) {
                    int u = tid + (i << 8);
                    int r = u >> 3;
                    int cb = (u & 7) << 4;
                    uint32_t off = ((r >> 3) << 10) + ((r & 7) << 7) + (cb ^ ((r & 7) << 4));
                    cp_async16(s + off, g + (size_t)r * rstride + cb);
                }
            }
            CP_COMMIT();
            CP_WAIT1();
        } else {
            CP_WAIT0();
        }
        __syncthreads();

        const uint32_t st  = su + (c & 1) * STAGE_B;
        const uint32_t SAh = st;
        const uint32_t SAl = st + TILE_B;
        const uint32_t SBh = st + 2 * TILE_B;
        const uint32_t SBl = st + 3 * TILE_B;

#pragma unroll
        for (int kp = 0; kp < 2; kp++) {
            uint32_t bh[4][4], bl[4][4];
#pragma unroll
            for (int n = 0; n < 4; n++) {
                uint32_t uB = 4*kp + uB_lo;
                uint32_t o = boff[n] + ((uB ^ br7[n]) << 4);
                ldsm4(bh[n], SBh + o);
                ldsm4(bl[n], SBl + o);
            }
#pragma unroll
            for (int ki = 0; ki < 2; ki++) {
                uint32_t uA = 2*(2*kp + ki) + uA_lo;
                uint32_t a[4][4];
#pragma unroll
                for (int m = 0; m < 4; m++)
                    ldsm4(a[m], SAh + aoff[m] + ((uA ^ ar7[m]) << 4));
#pragma unroll
                for (int m = 0; m < 4; m++)
#pragma unroll
                    for (int n = 0; n < 4; n++) {
                        mma16816(acc[m][n], a[m], bh[n][2*ki], bh[n][2*ki+1]);
                        mma16816(acc[m][n], a[m], bl[n][2*ki], bl[n][2*ki+1]);
                    }
#pragma unroll
                for (int m = 0; m < 4; m++)
                    ldsm4(a[m], SAl + aoff[m] + ((uA ^ ar7[m]) << 4));
#pragma unroll
                for (int m = 0; m < 4; m++)
#pragma unroll
                    for (int n = 0; n < 4; n++)
                        mma16816(acc[m][n], a[m], bh[n][2*ki], bh[n][2*ki+1]);
            }
        }
        __syncthreads();
    }

    if (Chi) {
        // split epilogue: write bf16 hi/lo directly
#pragma unroll
        for (int m = 0; m < 4; m++) {
            int rw = row0 + wm*64 + m*16 + (lane >> 2);
#pragma unroll
            for (int n = 0; n < 4; n++) {
                int cw = col0 + wn*32 + n*8 + ((lane & 3) << 1);
                *(uint32_t*)(Chi + (size_t)rw * No + cw) = pack_hi2(acc[m][n][0], acc[m][n][1]);
                *(uint32_t*)(Clo + (size_t)rw * No + cw) = pack_lo2(acc[m][n][0], acc[m][n][1]);
                *(uint32_t*)(Chi + (size_t)(rw + 8) * No + cw) = pack_hi2(acc[m][n][2], acc[m][n][3]);
                *(uint32_t*)(Clo + (size_t)(rw + 8) * No + cw) = pack_lo2(acc[m][n][2], acc[m][n][3]);
            }
        }
    } else {
#pragma unroll
        for (int m = 0; m < 4; m++) {
            int rw = row0 + wm*64 + m*16 + (lane >> 2);
#pragma unroll
            for (int n = 0; n < 4; n++) {
                int cw = col0 + wn*32 + n*8 + ((lane & 3) << 1);
                *(float2*)(C + (size_t)rw * No + cw) =
                    make_float2(acc[m][n][0], acc[m][n][1]);
                *(float2*)(C + (size_t)(rw + 8) * No + cw) =
                    make_float2(acc[m][n][2], acc[m][n][3]);
            }
        }
    }
}

// ---------------- fused RoPE + bf16 split (Q scaled by 1/sqrt(dh)) -----------
__global__ void rope_split(const int* __restrict__ pos,
                           const float* __restrict__ Q, const float* __restrict__ K,
                           __nv_bfloat162* __restrict__ qh, __nv_bfloat162* __restrict__ ql,
                           __nv_bfloat162* __restrict__ kh, __nv_bfloat162* __restrict__ kl)
{
    int idx = blockIdx.x * blockDim.x + threadIdx.x;
    int i = idx & 63;
    int hh = (idx >> 6) & 15;
    int l = (idx >> 10) & (Ll - 1);
    int b = idx >> 21;

    int p = pos[b * Ll + l];
    float ph = (float)p * g_invf[i];
    float s, c;
    sincosf(ph, &s, &c);

    size_t base = ((size_t)(b * Ll + l)) * Dm + hh * Dh + 2 * i;
    float q1 = Q[base], q2 = Q[base + 1];
    float k1 = K[base], k2 = K[base + 1];
    float qe = (q1 * c - q2 * s) * SCALE_C;
    float qo = (q1 * s + q2 * c) * SCALE_C;
    float ke = k1 * c - k2 * s;
    float ko = k1 * s + k2 * c;

    size_t o2 = base >> 1;
    uint32_t u;
    u = pack_hi2(qe, qo); qh[o2] = *reinterpret_cast<__nv_bfloat162*>(&u);
    u = pack_lo2(qe, qo); ql[o2] = *reinterpret_cast<__nv_bfloat162*>(&u);
    u = pack_hi2(ke, ko); kh[o2] = *reinterpret_cast<__nv_bfloat162*>(&u);
    u = pack_lo2(ke, ko); kl[o2] = *reinterpret_cast<__nv_bfloat162*>(&u);
}

// ---------------- tensor-core causal flash attention (bf16x3) ----------------
// CTA: 64 q-rows x one (b,h). 4 warps, each 16 q-rows. kv tiles of 64.
// SMEM: Qhi,Qlo,Khi,Klo,Vhi,Vlo tiles 64x128 bf16 (256B rows, XOR swizzle).
#define ATT_SMEM 98304

__global__ void __launch_bounds__(128, 2)
attn_mma(const __nv_bfloat16* __restrict__ Qh_g, const __nv_bfloat16* __restrict__ Ql_g,
         const __nv_bfloat16* __restrict__ Kh_g, const __nv_bfloat16* __restrict__ Kl_g,
         const __nv_bfloat16* __restrict__ Vh_g, const __nv_bfloat16* __restrict__ Vl_g,
         __nv_bfloat16* __restrict__ Ohi, __nv_bfloat16* __restrict__ Olo)
{
    extern __shared__ char sm[];
    const uint32_t su = smem_u32(sm);
    const uint32_t QH = 0, QL = 16384, KH = 32768, KL = 49152, VH = 65536, VL = 81920;

    const int tid = threadIdx.x, lane = tid & 31, wq = tid >> 5;
    const int qt = (int)(gridDim.x - 1 - blockIdx.x);
    const int h = blockIdx.y, b = blockIdx.z;
    const int qi0 = qt << 6;
    const size_t rowbase = (size_t)b * Ll;
    const int hoff = h * Dh;

    // ---- load Q tile hi/lo (rows=q, 256B rows, swizzle u^=(r&7) on low 3 bits)
#pragma unroll
    for (int i = 0; i < 8; i++) {
        int idx = tid + (i << 7);
        int r = idx >> 4, u = idx & 15;
        uint32_t so = r * 256 + ((u ^ (r & 7)) << 4);
        size_t go = (rowbase + qi0 + r) * Dm + hoff + u * 8;
        *(float4*)(sm + QH + so) = *(const float4*)(Qh_g + go);
        *(float4*)(sm + QL + so) = *(const float4*)(Ql_g + go);
    }

    float oacc[16][4];
#pragma unroll
    for (int t = 0; t < 16; t++)
#pragma unroll
        for (int q = 0; q < 4; q++) oacc[t][q] = 0.f;
    float m0 = -1e30f, m1 = -1e30f, l0 = 0.f, l1 = 0.f;

    for (int kt = 0; kt <= qt; kt++) {
        const int kj0 = kt << 6;
        __syncthreads();
#pragma unroll
        for (int i = 0; i < 8; i++) {
            int idx = tid + (i << 7);
            int r = idx >> 4, u = idx & 15;
            uint32_t so = r * 256 + ((u ^ (r & 7)) << 4);
            size_t go = (rowbase + kj0 + r) * Dm + hoff + u * 8;
            *(float4*)(sm + KH + so) = *(const float4*)(Kh_g + go);
            *(float4*)(sm + KL + so) = *(const float4*)(Kl_g + go);
            *(float4*)(sm + VH + so) = *(const float4*)(Vh_g + go);
            *(float4*)(sm + VL + so) = *(const float4*)(Vl_g + go);
        }
        __syncthreads();

        // ---- S = Q K^T (bf16x3)
        float sacc[8][4];
#pragma unroll
        for (int n = 0; n < 8; n++)
#pragma unroll
            for (int q = 0; q < 4; q++) sacc[n][q] = 0.f;

#pragma unroll
        for (int kg = 0; kg < 4; kg++) {
            uint32_t bh[8][4], bl[8][4];
#pragma unroll
            for (int n = 0; n < 8; n++) {
                int r = (n << 3) + (lane & 7);
                int u = (kg << 2) + (lane >> 3);
                uint32_t o = r * 256 + ((u ^ (r & 7)) << 4);
                ldsm4(bh[n], su + KH + o);
                ldsm4(bl[n], su + KL + o);
            }
#pragma unroll
            for (int ki = 0; ki < 2; ki++) {
                int r = (wq << 4) + (lane & 15);
                int u = ((2 * kg + ki) << 1) + (lane >> 4);
                uint32_t o = r * 256 + ((u ^ (r & 7)) << 4);
                uint32_t ah[4], al[4];
                ldsm4(ah, su + QH + o);
                ldsm4(al, su + QL + o);
#pragma unroll
                for (int n = 0; n < 8; n++) {
                    mma16816(sacc[n], ah, bh[n][2*ki], bh[n][2*ki+1]);
                    mma16816(sacc[n], ah, bl[n][2*ki], bl[n][2*ki+1]);
                    mma16816(sacc[n], al, bh[n][2*ki], bh[n][2*ki+1]);
                }
            }
        }

        // ---- causal mask (diag tile only; scale already folded into Q)
        if (kt == qt) {
            int r0 = (wq << 4) + (lane >> 2), r1 = r0 + 8;
            int cb = 2 * (lane & 3);
#pragma unroll
            for (int n = 0; n < 8; n++) {
                int c0 = (n << 3) + cb, c1 = c0 + 1;
                if (c0 > r0) sacc[n][0] = -1e30f;
                if (c1 > r0) sacc[n][1] = -1e30f;
                if (c0 > r1) sacc[n][2] = -1e30f;
                if (c1 > r1) sacc[n][3] = -1e30f;
            }
        }

        // ---- online softmax (fp32, quad shuffles)
        float mx0 = -1e30f, mx1 = -1e30f;
#pragma unroll
        for (int n = 0; n < 8; n++) {
            mx0 = fmaxf(mx0, fmaxf(sacc[n][0], sacc[n][1]));
            mx1 = fmaxf(mx1, fmaxf(sacc[n][2], sacc[n][3]));
        }
        mx0 = fmaxf(mx0, __shfl_xor_sync(0xffffffffu, mx0, 1));
        mx0 = fmaxf(mx0, __shfl_xor_sync(0xffffffffu, mx0, 2));
        mx1 = fmaxf(mx1, __shfl_xor_sync(0xffffffffu, mx1, 1));
        mx1 = fmaxf(mx1, __shfl_xor_sync(0xffffffffu, mx1, 2));
        float mn0 = fmaxf(m0, mx0), mn1 = fmaxf(m1, mx1);
        float al0 = __expf(m0 - mn0), al1 = __expf(m1 - mn1);
        float s0 = 0.f, s1 = 0.f;
#pragma unroll
        for (int n = 0; n < 8; n++) {
            sacc[n][0] = __expf(sacc[n][0] - mn0);
            sacc[n][1] = __expf(sacc[n][1] - mn0);
            sacc[n][2] = __expf(sacc[n][2] - mn1);
            sacc[n][3] = __expf(sacc[n][3] - mn1);
            s0 += sacc[n][0] + sacc[n][1];
            s1 += sacc[n][2] + sacc[n][3];
        }
        s0 += __shfl_xor_sync(0xffffffffu, s0, 1);
        s0 += __shfl_xor_sync(0xffffffffu, s0, 2);
        s1 += __shfl_xor_sync(0xffffffffu, s1, 1);
        s1 += __shfl_xor_sync(0xffffffffu, s1, 2);
        l0 = l0 * al0 + s0; l1 = l1 * al1 + s1;
        m0 = mn0; m1 = mn1;
#pragma unroll
        for (int t = 0; t < 16; t++) {
            oacc[t][0] *= al0; oacc[t][1] *= al0;
            oacc[t][2] *= al1; oacc[t][3] *= al1;
        }

        // ---- O += P V (P split hi/lo in regs, V^T b-frags via ldmatrix.trans)
#pragma unroll
        for (int ks = 0; ks < 4; ks++) {
            uint32_t ah[4], alr[4];
            ah[0]  = pack_hi2(sacc[2*ks][0],   sacc[2*ks][1]);
            ah[1]  = pack_hi2(sacc[2*ks][2],   sacc[2*ks][3]);
            ah[2]  = pack_hi2(sacc[2*ks+1][0], sacc[2*ks+1][1]);
            ah[3]  = pack_hi2(sacc[2*ks+1][2], sacc[2*ks+1][3]);
            alr[0] = pack_lo2(sacc[2*ks][0],   sacc[2*ks][1]);
            alr[1] = pack_lo2(sacc[2*ks][2],   sacc[2*ks][3]);
            alr[2] = pack_lo2(sacc[2*ks+1][0], sacc[2*ks+1][1]);
            alr[3] = pack_lo2(sacc[2*ks+1][2], sacc[2*ks+1][3]);
#pragma unroll
            for (int dg = 0; dg < 8; dg++) {
                int r = (ks << 4) + (lane & 15);
                int u = (dg << 1) + (lane >> 4);
                uint32_t o = r * 256 + ((u ^ (r & 7)) << 4);
                uint32_t bv[4], bw[4];
                ldsm4t(bv, su + VH + o);
                ldsm4t(bw, su + VL + o);
                mma16816(oacc[2*dg],   ah,  bv[0], bv[1]);
                mma16816(oacc[2*dg+1], ah,  bv[2], bv[3]);
                mma16816(oacc[2*dg],   ah,  bw[0], bw[1]);
                mma16816(oacc[2*dg+1], ah,  bw[2], bw[3]);
                mma16816(oacc[2*dg],   alr, bv[0], bv[1]);
                mma16816(oacc[2*dg+1], alr, bv[2], bv[3]);
            }
        }
    }

    // ---- epilogue: O/l -> bf16 hi/lo
    float i0 = 1.f / l0, i1 = 1.f / l1;
    size_t grow0 = rowbase + qi0 + (wq << 4) + (lane >> 2);
    size_t grow1 = grow0 + 8;
    int cb = hoff + 2 * (lane & 3);
#pragma unroll
    for (int t = 0; t < 16; t++) {
        int col = cb + (t << 3);
        float a = oacc[t][0] * i0, d = oacc[t][1] * i0;
        *(uint32_t*)(Ohi + grow0 * Dm + col) = pack_hi2(a, d);
        *(uint32_t*)(Olo + grow0 * Dm + col) = pack_lo2(a, d);
        float e = oacc[t][2] * i1, f = oacc[t][3] * i1;
        *(uint32_t*)(Ohi + grow1 * Dm + col) = pack_hi2(e, f);
        *(uint32_t*)(Olo + grow1 * Dm + col) = pack_lo2(e, f);
    }
}

// ---------------- launch ------------------------------------------------------
extern "C" void kernel_launch(void* const* d_in, const int* in_sizes, int n_in,
                              void* d_out, int out_size)
{
    const float* x  = (const float*)d_in[0];
    const int*  pos = (const int*)d_in[1];
    const float* Wq = (const float*)d_in[2];
    const float* Wk = (const float*)d_in[3];
    const float* Wv = (const float*)d_in[4];
    const float* Wo = (const float*)d_in[5];
    float* out = (float*)d_out;

    float *qp, *kp;
    __nv_bfloat16 *ahi, *alo, *whi, *wlo, *qhi, *qlo, *khi, *klo, *vhi, *vlo;
    cudaGetSymbolAddress((void**)&qp, g_Q);
    cudaGetSymbolAddress((void**)&kp, g_K);
    cudaGetSymbolAddress((void**)&ahi, g_ahi);
    cudaGetSymbolAddress((void**)&alo, g_alo);
    cudaGetSymbolAddress((void**)&whi, g_whi);
    cudaGetSymbolAddress((void**)&wlo, g_wlo);
    cudaGetSymbolAddress((void**)&qhi, g_qhi);
    cudaGetSymbolAddress((void**)&qlo, g_qlo);
    cudaGetSymbolAddress((void**)&khi, g_khi);
    cudaGetSymbolAddress((void**)&klo, g_klo);
    cudaGetSymbolAddress((void**)&vhi, g_vhi);
    cudaGetSymbolAddress((void**)&vlo, g_vlo);

    invf_kernel<<<1, 64>>>();

    const int nx4 = (Mm * Dm) / 4;
    const int nw4 = (Dm * Dm) / 4;

    cudaFuncSetAttribute(gemm_bf16x3,
                         cudaFuncAttributeMaxDynamicSharedMemorySize, GEMM_SMEM);
    cudaFuncSetAttribute(attn_mma,
                         cudaFuncAttributeMaxDynamicSharedMemorySize, ATT_SMEM);
    dim3 ggrid(Dm/128, Mm/128);

    // x -> bf16 hi/lo once
    split_bf16<<<nx4/256, 256>>>((const float4*)x,
                                 (__nv_bfloat162*)ahi, (__nv_bfloat162*)alo, nx4);

    // Q = x Wq^T (fp32 out, rope needs it)
    split_bf16<<<nw4/256, 256>>>((const float4*)Wq,
                                 (__nv_bfloat162*)whi, (__nv_bfloat162*)wlo, nw4);
    gemm_bf16x3<<<ggrid, 256, GEMM_SMEM>>>(ahi, alo, whi, wlo, qp,
                                           (__nv_bfloat16*)0, (__nv_bfloat16*)0, Dm, Dm);
    // K = x Wk^T (fp32 out)
    split_bf16<<<nw4/256, 256>>>((const float4*)Wk,
                                 (__nv_bfloat162*)whi, (__nv_bfloat162*)wlo, nw4);
    gemm_bf16x3<<<ggrid, 256, GEMM_SMEM>>>(ahi, alo, whi, wlo, kp,
                                           (__nv_bfloat16*)0, (__nv_bfloat16*)0, Dm, Dm);
    // V = x Wv^T (bf16 hi/lo directly)
    split_bf16<<<nw4/256, 256>>>((const float4*)Wv,
                                 (__nv_bfloat162*)whi, (__nv_bfloat162*)wlo, nw4);
    gemm_bf16x3<<<ggrid, 256, GEMM_SMEM>>>(ahi, alo, whi, wlo, (float*)0,
                                           vhi, vlo, Dm, Dm);

    // rope + split Q,K (Q scaled by 1/sqrt(dh))
    int npairs = Bb * Ll * Hn * (Dh/2);
    rope_split<<<npairs/256, 256>>>(pos, qp, kp,
                                    (__nv_bfloat162*)qhi, (__nv_bfloat162*)qlo,
                                    (__nv_bfloat162*)khi, (__nv_bfloat162*)klo);

    // attention -> O hi/lo into g_ahi/g_alo (x split no longer needed)
    dim3 agrid(Ll/64, Hn, Bb);
    attn_mma<<<agrid, 128, ATT_SMEM>>>(qhi, qlo, khi, klo, vhi, vlo, ahi, alo);

    // out = O Wo^T (fp32)
    split_bf16<<<nw4/256, 256>>>((const float4*)Wo,
                                 (__nv_bfloat162*)whi, (__nv_bfloat162*)wlo, nw4);
    gemm_bf16x3<<<ggrid, 256, GEMM_SMEM>>>(ahi, alo, whi, wlo, out,
                                           (__nv_bfloat16*)0, (__nv_bfloat16*)0, Dm, Dm);
}

// round 7
// speedup vs baseline: 5.5681x; 1.0449x over previous
#include <cuda_runtime.h>
#include <cuda_bf16.h>
#include <math.h>
#include <stdint.h>

#define Dm 2048
#define Hn 16
#define Dh 128
#define Bb 2
#define Ll 2048
#define Mm (Bb*Ll)   /* 4096 rows */
#define SCALE_C 0.08838834764831845f   /* 1/sqrt(128) */

// ---------------- scratch (static device globals; no runtime allocation) ----
__device__ __nv_bfloat16 g_ahi[(size_t)Mm * Dm];   // x split, later O split (hi)
__device__ __nv_bfloat16 g_alo[(size_t)Mm * Dm];
__device__ __nv_bfloat16 g_whi[(size_t)4 * Dm * Dm];   // Wq,Wk,Wv,Wo hi
__device__ __nv_bfloat16 g_wlo[(size_t)4 * Dm * Dm];
__device__ __nv_bfloat16 g_qhi[(size_t)Mm * Dm];
__device__ __nv_bfloat16 g_qlo[(size_t)Mm * Dm];
__device__ __nv_bfloat16 g_khi[(size_t)Mm * Dm];
__device__ __nv_bfloat16 g_klo[(size_t)Mm * Dm];
__device__ __nv_bfloat16 g_vhi[(size_t)Mm * Dm];
__device__ __nv_bfloat16 g_vlo[(size_t)Mm * Dm];
__device__ float g_invf[Dh/2];

// ======================= helpers =============================================
__device__ __forceinline__ uint32_t smem_u32(const void* p) {
    uint32_t a;
    asm("{ .reg .u64 t; cvta.to.shared.u64 t, %1; cvt.u32.u64 %0, t; }"
        : "=r"(a) : "l"(p));
    return a;
}
__device__ __forceinline__ void cp_async16(uint32_t saddr, const void* gaddr) {
    asm volatile("cp.async.cg.shared.global [%0], [%1], 16;"
                 :: "r"(saddr), "l"(gaddr) : "memory");
}
#define CP_COMMIT() asm volatile("cp.async.commit_group;" ::: "memory")
#define CP_WAIT1()  asm volatile("cp.async.wait_group 1;" ::: "memory")
#define CP_WAIT0()  asm volatile("cp.async.wait_group 0;" ::: "memory")

__device__ __forceinline__ void ldsm4(uint32_t* d, uint32_t a) {
    asm volatile("ldmatrix.sync.aligned.m8n8.x4.shared.b16 {%0,%1,%2,%3}, [%4];"
                 : "=r"(d[0]), "=r"(d[1]), "=r"(d[2]), "=r"(d[3]) : "r"(a));
}
__device__ __forceinline__ void ldsm4t(uint32_t* d, uint32_t a) {
    asm volatile("ldmatrix.sync.aligned.m8n8.x4.trans.shared.b16 {%0,%1,%2,%3}, [%4];"
                 : "=r"(d[0]), "=r"(d[1]), "=r"(d[2]), "=r"(d[3]) : "r"(a));
}
__device__ __forceinline__ void mma16816(float* d, const uint32_t* a,
                                         uint32_t b0, uint32_t b1) {
    asm volatile(
        "mma.sync.aligned.m16n8k16.row.col.f32.bf16.bf16.f32 "
        "{%0,%1,%2,%3}, {%4,%5,%6,%7}, {%8,%9}, {%0,%1,%2,%3};"
        : "+f"(d[0]), "+f"(d[1]), "+f"(d[2]), "+f"(d[3])
        : "r"(a[0]), "r"(a[1]), "r"(a[2]), "r"(a[3]), "r"(b0), "r"(b1));
}
__device__ __forceinline__ uint32_t pack_hi2(float a, float b) {
    __nv_bfloat162 t = __floats2bfloat162_rn(a, b);
    return *reinterpret_cast<uint32_t*>(&t);
}
__device__ __forceinline__ uint32_t pack_lo2(float a, float b) {
    float ra = a - __bfloat162float(__float2bfloat16_rn(a));
    float rb = b - __bfloat162float(__float2bfloat16_rn(b));
    __nv_bfloat162 t = __floats2bfloat162_rn(ra, rb);
    return *reinterpret_cast<uint32_t*>(&t);
}

// ---------------- inv_freq table --------------------------------------------
__global__ void invf_kernel() {
    int i = threadIdx.x;
    if (i < Dh/2)
        g_invf[i] = (float)pow(10000.0, -(double)(2*i) / (double)Dh);
}

// ---------------- fp32 -> bf16 hi/lo split (single tensor) -------------------
__global__ void split_bf16(const float4* __restrict__ src,
                           __nv_bfloat162* __restrict__ hi,
                           __nv_bfloat162* __restrict__ lo, int n4)
{
    int i = blockIdx.x * blockDim.x + threadIdx.x;
    if (i >= n4) return;
    float4 v = src[i];
    hi[2*i]   = *(__nv_bfloat162*)&(uint32_t&)*(uint32_t[]){pack_hi2(v.x, v.y)};
    // (expanded below for clarity)
    uint32_t h0 = pack_hi2(v.x, v.y), h1 = pack_hi2(v.z, v.w);
    uint32_t l0 = pack_lo2(v.x, v.y), l1 = pack_lo2(v.z, v.w);
    hi[2*i]   = *reinterpret_cast<__nv_bfloat162*>(&h0);
    hi[2*i+1] = *reinterpret_cast<__nv_bfloat162*>(&h1);
    lo[2*i]   = *reinterpret_cast<__nv_bfloat162*>(&l0);
    lo[2*i+1] = *reinterpret_cast<__nv_bfloat162*>(&l1);
}

// ---------------- split all 4 weights into packed hi/lo ----------------------
__global__ void split4_w(const float4* __restrict__ w0, const float4* __restrict__ w1,
                         const float4* __restrict__ w2, const float4* __restrict__ w3,
                         __nv_bfloat162* __restrict__ hi, __nv_bfloat162* __restrict__ lo)
{
    const int n4each = (Dm * Dm) / 4;     // 2^20
    int idx = blockIdx.x * blockDim.x + threadIdx.x;
    int t = idx >> 20;
    int r = idx & (n4each - 1);
    const float4* s = (t == 0) ? w0 : (t == 1) ? w1 : (t == 2) ? w2 : w3;
    float4 v = s[r];
    uint32_t h0 = pack_hi2(v.x, v.y), h1 = pack_hi2(v.z, v.w);
    uint32_t l0 = pack_lo2(v.x, v.y), l1 = pack_lo2(v.z, v.w);
    hi[2*(size_t)idx]   = *reinterpret_cast<__nv_bfloat162*>(&h0);
    hi[2*(size_t)idx+1] = *reinterpret_cast<__nv_bfloat162*>(&h1);
    lo[2*(size_t)idx]   = *reinterpret_cast<__nv_bfloat162*>(&l0);
    lo[2*(size_t)idx+1] = *reinterpret_cast<__nv_bfloat162*>(&l1);
}

// ============== shared GEMM mainloop (bf16x3, 3-stage cp.async) ==============
#define KC 64
#define TILE_B 16384
#define STAGE_B (4*TILE_B)
#define GEMM_SMEM (1024 + 3*STAGE_B)

// issues loads of chunk `c` into stage buffer
#define ISSUE_CHUNK(cc) do {                                                   \
    uint32_t sbase = su + ((cc) % 3) * STAGE_B;                                \
    const size_t kb = (size_t)(cc) * (KC * 2);                                 \
    _Pragma("unroll")                                                          \
    for (int t = 0; t < 4; t++) {                                              \
        const char* g = srcs[t] + kb;                                          \
        uint32_t s = sbase + t * TILE_B;                                       \
        _Pragma("unroll")                                                      \
        for (int i = 0; i < 4; i++) {                                          \
            int u = tid + (i << 8);                                            \
            int r = u >> 3;                                                    \
            int cb = (u & 7) << 4;                                             \
            uint32_t off = ((r >> 3) << 10) + ((r & 7) << 7) + (cb ^ ((r & 7) << 4)); \
            cp_async16(s + off, g + (size_t)r * rstride + cb);                 \
        }                                                                      \
    }                                                                          \
    CP_COMMIT();                                                               \
} while (0)

#define GEMM_MAINLOOP()                                                        \
    uint32_t aoff[4], ar7[4];                                                  \
    _Pragma("unroll")                                                          \
    for (int m = 0; m < 4; m++) {                                              \
        int r = wm*64 + m*16 + (lane & 15);                                    \
        aoff[m] = ((r >> 3) << 10) + ((r & 7) << 7);                           \
        ar7[m]  = r & 7;                                                       \
    }                                                                          \
    uint32_t boff[4], br7[4];                                                  \
    _Pragma("unroll")                                                          \
    for (int n = 0; n < 4; n++) {                                              \
        int r = wn*32 + n*8 + (lane & 7);                                      \
        boff[n] = ((r >> 3) << 10) + ((r & 7) << 7);                           \
        br7[n]  = r & 7;                                                       \
    }                                                                          \
    const uint32_t uA_lo = lane >> 4;                                          \
    const uint32_t uB_lo = lane >> 3;                                          \
    float acc[4][4][4];                                                        \
    _Pragma("unroll")                                                          \
    for (int m = 0; m < 4; m++)                                                \
        _Pragma("unroll")                                                      \
        for (int n = 0; n < 4; n++)                                            \
            _Pragma("unroll")                                                  \
            for (int q = 0; q < 4; q++) acc[m][n][q] = 0.f;                    \
    const int NCH = Ko / KC;                                                   \
    ISSUE_CHUNK(0);                                                            \
    ISSUE_CHUNK(1);                                                            \
    for (int c = 0; c < NCH; c++) {                                            \
        if (c < NCH - 1) { CP_WAIT1(); } else { CP_WAIT0(); }                  \
        __syncthreads();                                                       \
        if (c + 2 < NCH) ISSUE_CHUNK(c + 2);                                   \
        const uint32_t st  = su + (c % 3) * STAGE_B;                           \
        const uint32_t SAh = st;                                               \
        const uint32_t SAl = st + TILE_B;                                      \
        const uint32_t SBh = st + 2 * TILE_B;                                  \
        const uint32_t SBl = st + 3 * TILE_B;                                  \
        _Pragma("unroll")                                                      \
        for (int kp = 0; kp < 2; kp++) {                                       \
            uint32_t bh[4][4], bl[4][4];                                       \
            _Pragma("unroll")                                                  \
            for (int n = 0; n < 4; n++) {                                      \
                uint32_t uB = 4*kp + uB_lo;                                    \
                uint32_t o = boff[n] + ((uB ^ br7[n]) << 4);                   \
                ldsm4(bh[n], SBh + o);                                         \
                ldsm4(bl[n], SBl + o);                                         \
            }                                                                  \
            _Pragma("unroll")                                                  \
            for (int ki = 0; ki < 2; ki++) {                                   \
                uint32_t uA = 2*(2*kp + ki) + uA_lo;                           \
                uint32_t a[4][4];                                              \
                _Pragma("unroll")                                              \
                for (int m = 0; m < 4; m++)                                    \
                    ldsm4(a[m], SAh + aoff[m] + ((uA ^ ar7[m]) << 4));         \
                _Pragma("unroll")                                              \
                for (int m = 0; m < 4; m++)                                    \
                    _Pragma("unroll")                                          \
                    for (int n = 0; n < 4; n++) {                              \
                        mma16816(acc[m][n], a[m], bh[n][2*ki], bh[n][2*ki+1]); \
                        mma16816(acc[m][n], a[m], bl[n][2*ki], bl[n][2*ki+1]); \
                    }                                                          \
                _Pragma("unroll")                                              \
                for (int m = 0; m < 4; m++)                                    \
                    ldsm4(a[m], SAl + aoff[m] + ((uA ^ ar7[m]) << 4));         \
                _Pragma("unroll")                                              \
                for (int m = 0; m < 4; m++)                                    \
                    _Pragma("unroll")                                          \
                    for (int n = 0; n < 4; n++)                                \
                        mma16816(acc[m][n], a[m], bh[n][2*ki], bh[n][2*ki+1]); \
            }                                                                  \
        }                                                                      \
        __syncthreads();                                                       \
    }

// ---------------- fused QKV GEMM + RoPE + bf16 split epilogue ----------------
// grid (16, 32, 3): z=0 Q (rope+scale), z=1 K (rope), z=2 V (plain split)
__global__ void __launch_bounds__(256, 1)
gemm_qkv(const __nv_bfloat16* __restrict__ Ahi, const __nv_bfloat16* __restrict__ Alo,
         const __nv_bfloat16* __restrict__ Whi_all, const __nv_bfloat16* __restrict__ Wlo_all,
         const int* __restrict__ pos,
         __nv_bfloat16* __restrict__ Qh, __nv_bfloat16* __restrict__ Ql,
         __nv_bfloat16* __restrict__ Kh, __nv_bfloat16* __restrict__ Kl,
         __nv_bfloat16* __restrict__ Vh, __nv_bfloat16* __restrict__ Vl)
{
    extern __shared__ char smraw[];
    char* smal = (char*)(((uintptr_t)smraw + 1023) & ~(uintptr_t)1023);
    const uint32_t su = smem_u32(smal);

    const int tid = threadIdx.x;
    const int lane = tid & 31, wid = tid >> 5;
    const int row0 = blockIdx.y << 7;
    const int col0 = blockIdx.x << 7;
    const int z = blockIdx.z;
    const int wm = wid >> 2, wn = wid & 3;
    const int Ko = Dm;

    const char* srcs[4];
    srcs[0] = (const char*)(Ahi + (size_t)row0 * Ko);
    srcs[1] = (const char*)(Alo + (size_t)row0 * Ko);
    srcs[2] = (const char*)(Whi_all + (size_t)z * Dm * Dm + (size_t)col0 * Ko);
    srcs[3] = (const char*)(Wlo_all + (size_t)z * Dm * Dm + (size_t)col0 * Ko);
    const size_t rstride = (size_t)Ko * 2;

    GEMM_MAINLOOP();

    if (z == 2) {
        // V: plain bf16 hi/lo split
#pragma unroll
        for (int m = 0; m < 4; m++) {
            int rw = row0 + wm*64 + m*16 + (lane >> 2);
#pragma unroll
            for (int n = 0; n < 4; n++) {
                int cw = col0 + wn*32 + n*8 + ((lane & 3) << 1);
                *(uint32_t*)(Vh + (size_t)rw * Dm + cw) = pack_hi2(acc[m][n][0], acc[m][n][1]);
                *(uint32_t*)(Vl + (size_t)rw * Dm + cw) = pack_lo2(acc[m][n][0], acc[m][n][1]);
                *(uint32_t*)(Vh + (size_t)(rw+8) * Dm + cw) = pack_hi2(acc[m][n][2], acc[m][n][3]);
                *(uint32_t*)(Vl + (size_t)(rw+8) * Dm + cw) = pack_lo2(acc[m][n][2], acc[m][n][3]);
            }
        }
    } else {
        // Q/K: RoPE (+ scale for Q) then split. Columns come in (even,odd) pairs.
        __nv_bfloat16* Dhi = (z == 0) ? Qh : Kh;
        __nv_bfloat16* Dlo = (z == 0) ? Ql : Kl;
        const float scl = (z == 0) ? SCALE_C : 1.0f;
#pragma unroll
        for (int m = 0; m < 4; m++) {
            int rw = row0 + wm*64 + m*16 + (lane >> 2);
            float p0 = (float)pos[rw];
            float p1 = (float)pos[rw + 8];
#pragma unroll
            for (int n = 0; n < 4; n++) {
                int cw = col0 + wn*32 + n*8 + ((lane & 3) << 1);
                float inv = g_invf[(cw & 127) >> 1];
                float s0, c0, s1, c1;
                sincosf(p0 * inv, &s0, &c0);
                sincosf(p1 * inv, &s1, &c1);
                float e = acc[m][n][0], o = acc[m][n][1];
                float re = (e*c0 - o*s0) * scl, ro = (e*s0 + o*c0) * scl;
                *(uint32_t*)(Dhi + (size_t)rw * Dm + cw) = pack_hi2(re, ro);
                *(uint32_t*)(Dlo + (size_t)rw * Dm + cw) = pack_lo2(re, ro);
                e = acc[m][n][2]; o = acc[m][n][3];
                re = (e*c1 - o*s1) * scl; ro = (e*s1 + o*c1) * scl;
                *(uint32_t*)(Dhi + (size_t)(rw+8) * Dm + cw) = pack_hi2(re, ro);
                *(uint32_t*)(Dlo + (size_t)(rw+8) * Dm + cw) = pack_lo2(re, ro);
            }
        }
    }
}

// ---------------- plain bf16x3 GEMM (fp32 out) for the Wo projection ---------
__global__ void __launch_bounds__(256, 1)
gemm_bf16x3(const __nv_bfloat16* __restrict__ Ahi, const __nv_bfloat16* __restrict__ Alo,
            const __nv_bfloat16* __restrict__ Bhi, const __nv_bfloat16* __restrict__ Blo,
            float* __restrict__ C, int Ko, int No)
{
    extern __shared__ char smraw[];
    char* smal = (char*)(((uintptr_t)smraw + 1023) & ~(uintptr_t)1023);
    const uint32_t su = smem_u32(smal);

    const int tid = threadIdx.x;
    const int lane = tid & 31, wid = tid >> 5;
    const int row0 = blockIdx.y << 7;
    const int col0 = blockIdx.x << 7;
    const int wm = wid >> 2, wn = wid & 3;

    const char* srcs[4];
    srcs[0] = (const char*)(Ahi + (size_t)row0 * Ko);
    srcs[1] = (const char*)(Alo + (size_t)row0 * Ko);
    srcs[2] = (const char*)(Bhi + (size_t)col0 * Ko);
    srcs[3] = (const char*)(Blo + (size_t)col0 * Ko);
    const size_t rstride = (size_t)Ko * 2;

    GEMM_MAINLOOP();

#pragma unroll
    for (int m = 0; m < 4; m++) {
        int rw = row0 + wm*64 + m*16 + (lane >> 2);
#pragma unroll
        for (int n = 0; n < 4; n++) {
            int cw = col0 + wn*32 + n*8 + ((lane & 3) << 1);
            *(float2*)(C + (size_t)rw * No + cw) =
                make_float2(acc[m][n][0], acc[m][n][1]);
            *(float2*)(C + (size_t)(rw + 8) * No + cw) =
                make_float2(acc[m][n][2], acc[m][n][3]);
        }
    }
}

// ---------------- tensor-core causal flash attention (bf16x3) ----------------
#define ATT_SMEM 98304

__global__ void __launch_bounds__(128, 2)
attn_mma(const __nv_bfloat16* __restrict__ Qh_g, const __nv_bfloat16* __restrict__ Ql_g,
         const __nv_bfloat16* __restrict__ Kh_g, const __nv_bfloat16* __restrict__ Kl_g,
         const __nv_bfloat16* __restrict__ Vh_g, const __nv_bfloat16* __restrict__ Vl_g,
         __nv_bfloat16* __restrict__ Ohi, __nv_bfloat16* __restrict__ Olo)
{
    extern __shared__ char sm[];
    const uint32_t su = smem_u32(sm);
    const uint32_t QH = 0, QL = 16384, KH = 32768, KL = 49152, VH = 65536, VL = 81920;

    const int tid = threadIdx.x, lane = tid & 31, wq = tid >> 5;
    const int qt = (int)(gridDim.x - 1 - blockIdx.x);
    const int h = blockIdx.y, b = blockIdx.z;
    const int qi0 = qt << 6;
    const size_t rowbase = (size_t)b * Ll;
    const int hoff = h * Dh;

#pragma unroll
    for (int i = 0; i < 8; i++) {
        int idx = tid + (i << 7);
        int r = idx >> 4, u = idx & 15;
        uint32_t so = r * 256 + ((u ^ (r & 7)) << 4);
        size_t go = (rowbase + qi0 + r) * Dm + hoff + u * 8;
        *(float4*)(sm + QH + so) = *(const float4*)(Qh_g + go);
        *(float4*)(sm + QL + so) = *(const float4*)(Ql_g + go);
    }

    float oacc[16][4];
#pragma unroll
    for (int t = 0; t < 16; t++)
#pragma unroll
        for (int q = 0; q < 4; q++) oacc[t][q] = 0.f;
    float m0 = -1e30f, m1 = -1e30f, l0 = 0.f, l1 = 0.f;

    for (int kt = 0; kt <= qt; kt++) {
        const int kj0 = kt << 6;
        __syncthreads();
#pragma unroll
        for (int i = 0; i < 8; i++) {
            int idx = tid + (i << 7);
            int r = idx >> 4, u = idx & 15;
            uint32_t so = r * 256 + ((u ^ (r & 7)) << 4);
            size_t go = (rowbase + kj0 + r) * Dm + hoff + u * 8;
            *(float4*)(sm + KH + so) = *(const float4*)(Kh_g + go);
            *(float4*)(sm + KL + so) = *(const float4*)(Kl_g + go);
            *(float4*)(sm + VH + so) = *(const float4*)(Vh_g + go);
            *(float4*)(sm + VL + so) = *(const float4*)(Vl_g + go);
        }
        __syncthreads();

        float sacc[8][4];
#pragma unroll
        for (int n = 0; n < 8; n++)
#pragma unroll
            for (int q = 0; q < 4; q++) sacc[n][q] = 0.f;

#pragma unroll
        for (int kg = 0; kg < 4; kg++) {
            uint32_t bh[8][4], bl[8][4];
#pragma unroll
            for (int n = 0; n < 8; n++) {
                int r = (n << 3) + (lane & 7);
                int u = (kg << 2) + (lane >> 3);
                uint32_t o = r * 256 + ((u ^ (r & 7)) << 4);
                ldsm4(bh[n], su + KH + o);
                ldsm4(bl[n], su + KL + o);
            }
#pragma unroll
            for (int ki = 0; ki < 2; ki++) {
                int r = (wq << 4) + (lane & 15);
                int u = ((2 * kg + ki) << 1) + (lane >> 4);
                uint32_t o = r * 256 + ((u ^ (r & 7)) << 4);
                uint32_t ah[4], al[4];
                ldsm4(ah, su + QH + o);
                ldsm4(al, su + QL + o);
#pragma unroll
                for (int n = 0; n < 8; n++) {
                    mma16816(sacc[n], ah, bh[n][2*ki], bh[n][2*ki+1]);
                    mma16816(sacc[n], ah, bl[n][2*ki], bl[n][2*ki+1]);
                    mma16816(sacc[n], al, bh[n][2*ki], bh[n][2*ki+1]);
                }
            }
        }

        if (kt == qt) {
            int r0 = (wq << 4) + (lane >> 2), r1 = r0 + 8;
            int cb = 2 * (lane & 3);
#pragma unroll
            for (int n = 0; n < 8; n++) {
                int c0 = (n << 3) + cb, c1 = c0 + 1;
                if (c0 > r0) sacc[n][0] = -1e30f;
                if (c1 > r0) sacc[n][1] = -1e30f;
                if (c0 > r1) sacc[n][2] = -1e30f;
                if (c1 > r1) sacc[n][3] = -1e30f;
            }
        }

        float mx0 = -1e30f, mx1 = -1e30f;
#pragma unroll
        for (int n = 0; n < 8; n++) {
            mx0 = fmaxf(mx0, fmaxf(sacc[n][0], sacc[n][1]));
            mx1 = fmaxf(mx1, fmaxf(sacc[n][2], sacc[n][3]));
        }
        mx0 = fmaxf(mx0, __shfl_xor_sync(0xffffffffu, mx0, 1));
        mx0 = fmaxf(mx0, __shfl_xor_sync(0xffffffffu, mx0, 2));
        mx1 = fmaxf(mx1, __shfl_xor_sync(0xffffffffu, mx1, 1));
        mx1 = fmaxf(mx1, __shfl_xor_sync(0xffffffffu, mx1, 2));
        float mn0 = fmaxf(m0, mx0), mn1 = fmaxf(m1, mx1);
        float al0 = __expf(m0 - mn0), al1 = __expf(m1 - mn1);
        float s0 = 0.f, s1 = 0.f;
#pragma unroll
        for (int n = 0; n < 8; n++) {
            sacc[n][0] = __expf(sacc[n][0] - mn0);
            sacc[n][1] = __expf(sacc[n][1] - mn0);
            sacc[n][2] = __expf(sacc[n][2] - mn1);
            sacc[n][3] = __expf(sacc[n][3] - mn1);
            s0 += sacc[n][0] + sacc[n][1];
            s1 += sacc[n][2] + sacc[n][3];
        }
        s0 += __shfl_xor_sync(0xffffffffu, s0, 1);
        s0 += __shfl_xor_sync(0xffffffffu, s0, 2);
        s1 += __shfl_xor_sync(0xffffffffu, s1, 1);
        s1 += __shfl_xor_sync(0xffffffffu, s1, 2);
        l0 = l0 * al0 + s0; l1 = l1 * al1 + s1;
        m0 = mn0; m1 = mn1;
#pragma unroll
        for (int t = 0; t < 16; t++) {
            oacc[t][0] *= al0; oacc[t][1] *= al0;
            oacc[t][2] *= al1; oacc[t][3] *= al1;
        }

#pragma unroll
        for (int ks = 0; ks < 4; ks++) {
            uint32_t ah[4], alr[4];
            ah[0]  = pack_hi2(sacc[2*ks][0],   sacc[2*ks][1]);
            ah[1]  = pack_hi2(sacc[2*ks][2],   sacc[2*ks][3]);
            ah[2]  = pack_hi2(sacc[2*ks+1][0], sacc[2*ks+1][1]);
            ah[3]  = pack_hi2(sacc[2*ks+1][2], sacc[2*ks+1][3]);
            alr[0] = pack_lo2(sacc[2*ks][0],   sacc[2*ks][1]);
            alr[1] = pack_lo2(sacc[2*ks][2],   sacc[2*ks][3]);
            alr[2] = pack_lo2(sacc[2*ks+1][0], sacc[2*ks+1][1]);
            alr[3] = pack_lo2(sacc[2*ks+1][2], sacc[2*ks+1][3]);
#pragma unroll
            for (int dg = 0; dg < 8; dg++) {
                int r = (ks << 4) + (lane & 15);
                int u = (dg << 1) + (lane >> 4);
                uint32_t o = r * 256 + ((u ^ (r & 7)) << 4);
                uint32_t bv[4], bw[4];
                ldsm4t(bv, su + VH + o);
                ldsm4t(bw, su + VL + o);
                mma16816(oacc[2*dg],   ah,  bv[0], bv[1]);
                mma16816(oacc[2*dg+1], ah,  bv[2], bv[3]);
                mma16816(oacc[2*dg],   ah,  bw[0], bw[1]);
                mma16816(oacc[2*dg+1], ah,  bw[2], bw[3]);
                mma16816(oacc[2*dg],   alr, bv[0], bv[1]);
                mma16816(oacc[2*dg+1], alr, bv[2], bv[3]);
            }
        }
    }

    float i0 = 1.f / l0, i1 = 1.f / l1;
    size_t grow0 = rowbase + qi0 + (wq << 4) + (lane >> 2);
    size_t grow1 = grow0 + 8;
    int cb = hoff + 2 * (lane & 3);
#pragma unroll
    for (int t = 0; t < 16; t++) {
        int col = cb + (t << 3);
        float a = oacc[t][0] * i0, d = oacc[t][1] * i0;
        *(uint32_t*)(Ohi + grow0 * Dm + col) = pack_hi2(a, d);
        *(uint32_t*)(Olo + grow0 * Dm + col) = pack_lo2(a, d);
        float e = oacc[t][2] * i1, f = oacc[t][3] * i1;
        *(uint32_t*)(Ohi + grow1 * Dm + col) = pack_hi2(e, f);
        *(uint32_t*)(Olo + grow1 * Dm + col) = pack_lo2(e, f);
    }
}

// ---------------- launch ------------------------------------------------------
extern "C" void kernel_launch(void* const* d_in, const int* in_sizes, int n_in,
                              void* d_out, int out_size)
{
    const float* x  = (const float*)d_in[0];
    const int*  pos = (const int*)d_in[1];
    const float* Wq = (const float*)d_in[2];
    const float* Wk = (const float*)d_in[3];
    const float* Wv = (const float*)d_in[4];
    const float* Wo = (const float*)d_in[5];
    float* out = (float*)d_out;

    __nv_bfloat16 *ahi, *alo, *whi, *wlo, *qhi, *qlo, *khi, *klo, *vhi, *vlo;
    cudaGetSymbolAddress((void**)&ahi, g_ahi);
    cudaGetSymbolAddress((void**)&alo, g_alo);
    cudaGetSymbolAddress((void**)&whi, g_whi);
    cudaGetSymbolAddress((void**)&wlo, g_wlo);
    cudaGetSymbolAddress((void**)&qhi, g_qhi);
    cudaGetSymbolAddress((void**)&qlo, g_qlo);
    cudaGetSymbolAddress((void**)&khi, g_khi);
    cudaGetSymbolAddress((void**)&klo, g_klo);
    cudaGetSymbolAddress((void**)&vhi, g_vhi);
    cudaGetSymbolAddress((void**)&vlo, g_vlo);

    invf_kernel<<<1, 64>>>();

    const int nx4 = (Mm * Dm) / 4;
    const int nw4 = (Dm * Dm) / 4;

    cudaFuncSetAttribute(gemm_qkv,
                         cudaFuncAttributeMaxDynamicSharedMemorySize, GEMM_SMEM);
    cudaFuncSetAttribute(gemm_bf16x3,
                         cudaFuncAttributeMaxDynamicSharedMemorySize, GEMM_SMEM);
    cudaFuncSetAttribute(attn_mma,
                         cudaFuncAttributeMaxDynamicSharedMemorySize, ATT_SMEM);

    // x -> bf16 hi/lo
    split_bf16<<<nx4/256, 256>>>((const float4*)x,
                                 (__nv_bfloat162*)ahi, (__nv_bfloat162*)alo, nx4);
    // all 4 weights -> packed bf16 hi/lo
    split4_w<<<(4*nw4)/256, 256>>>((const float4*)Wq, (const float4*)Wk,
                                   (const float4*)Wv, (const float4*)Wo,
                                   (__nv_bfloat162*)whi, (__nv_bfloat162*)wlo);

    // fused QKV GEMM + RoPE + split (one launch, 1536 CTAs)
    dim3 qkvgrid(Dm/128, Mm/128, 3);
    gemm_qkv<<<qkvgrid, 256, GEMM_SMEM>>>(ahi, alo, whi, wlo, pos,
                                          qhi, qlo, khi, klo, vhi, vlo);

    // attention -> O hi/lo into g_ahi/g_alo
    dim3 agrid(Ll/64, Hn, Bb);
    attn_mma<<<agrid, 128, ATT_SMEM>>>(qhi, qlo, khi, klo, vhi, vlo, ahi, alo);

    // out = O Wo^T (fp32)
    dim3 ggrid(Dm/128, Mm/128);
    gemm_bf16x3<<<ggrid, 256, GEMM_SMEM>>>(ahi, alo,
                                           whi + (size_t)3*Dm*Dm, wlo + (size_t)3*Dm*Dm,
                                           out, Dm, Dm);
}

// round 8
// speedup vs baseline: 7.7145x; 1.3855x over previous
#include <cuda_runtime.h>
#include <cuda_fp16.h>
#include <math.h>
#include <stdint.h>

#define Dm 2048
#define Hn 16
#define Dh 128
#define Bb 2
#define Ll 2048
#define Mm (Bb*Ll)   /* 4096 rows */
#define SCALE_C 0.08838834764831845f   /* 1/sqrt(128) */

// ---------------- scratch (static device globals; no runtime allocation) ----
__device__ __half g_ahi[(size_t)Mm * Dm];   // x split hi, later O split hi
__device__ __half g_alo[(size_t)Mm * Dm];
__device__ __half g_w[(size_t)4 * Dm * Dm]; // Wq,Wk,Wv,Wo single fp16
__device__ __half g_qhi[(size_t)Mm * Dm];
__device__ __half g_qlo[(size_t)Mm * Dm];
__device__ __half g_k[(size_t)Mm * Dm];     // K single fp16 (post-rope)
__device__ __half g_v[(size_t)Mm * Dm];     // V single fp16
__device__ float g_invf[Dh/2];

// ======================= helpers =============================================
__device__ __forceinline__ uint32_t smem_u32(const void* p) {
    uint32_t a;
    asm("{ .reg .u64 t; cvta.to.shared.u64 t, %1; cvt.u32.u64 %0, t; }"
        : "=r"(a) : "l"(p));
    return a;
}
__device__ __forceinline__ void cp_async16(uint32_t saddr, const void* gaddr) {
    asm volatile("cp.async.cg.shared.global [%0], [%1], 16;"
                 :: "r"(saddr), "l"(gaddr) : "memory");
}
#define CP_COMMIT() asm volatile("cp.async.commit_group;" ::: "memory")
#define CP_WAIT1()  asm volatile("cp.async.wait_group 1;" ::: "memory")
#define CP_WAIT0()  asm volatile("cp.async.wait_group 0;" ::: "memory")

__device__ __forceinline__ void ldsm4(uint32_t* d, uint32_t a) {
    asm volatile("ldmatrix.sync.aligned.m8n8.x4.shared.b16 {%0,%1,%2,%3}, [%4];"
                 : "=r"(d[0]), "=r"(d[1]), "=r"(d[2]), "=r"(d[3]) : "r"(a));
}
__device__ __forceinline__ void ldsm4t(uint32_t* d, uint32_t a) {
    asm volatile("ldmatrix.sync.aligned.m8n8.x4.trans.shared.b16 {%0,%1,%2,%3}, [%4];"
                 : "=r"(d[0]), "=r"(d[1]), "=r"(d[2]), "=r"(d[3]) : "r"(a));
}
__device__ __forceinline__ void mma16816(float* d, const uint32_t* a,
                                         uint32_t b0, uint32_t b1) {
    asm volatile(
        "mma.sync.aligned.m16n8k16.row.col.f32.f16.f16.f32 "
        "{%0,%1,%2,%3}, {%4,%5,%6,%7}, {%8,%9}, {%0,%1,%2,%3};"
        : "+f"(d[0]), "+f"(d[1]), "+f"(d[2]), "+f"(d[3])
        : "r"(a[0]), "r"(a[1]), "r"(a[2]), "r"(a[3]), "r"(b0), "r"(b1));
}
__device__ __forceinline__ uint32_t pack_hi2h(float a, float b) {
    __half2 t = __floats2half2_rn(a, b);
    return *reinterpret_cast<uint32_t*>(&t);
}
__device__ __forceinline__ uint32_t pack_lo2h(float a, float b) {
    float ra = a - __half2float(__float2half_rn(a));
    float rb = b - __half2float(__float2half_rn(b));
    __half2 t = __floats2half2_rn(ra, rb);
    return *reinterpret_cast<uint32_t*>(&t);
}

// ---------------- inv_freq table --------------------------------------------
__global__ void invf_kernel() {
    int i = threadIdx.x;
    if (i < Dh/2)
        g_invf[i] = (float)pow(10000.0, -(double)(2*i) / (double)Dh);
}

// ---------------- fp32 -> fp16 hi/lo split (x) --------------------------------
__global__ void split_x(const float4* __restrict__ src,
                        __half2* __restrict__ hi, __half2* __restrict__ lo, int n4)
{
    int i = blockIdx.x * blockDim.x + threadIdx.x;
    if (i >= n4) return;
    float4 v = src[i];
    uint32_t h0 = pack_hi2h(v.x, v.y), h1 = pack_hi2h(v.z, v.w);
    uint32_t l0 = pack_lo2h(v.x, v.y), l1 = pack_lo2h(v.z, v.w);
    hi[2*i]   = *reinterpret_cast<__half2*>(&h0);
    hi[2*i+1] = *reinterpret_cast<__half2*>(&h1);
    lo[2*i]   = *reinterpret_cast<__half2*>(&l0);
    lo[2*i+1] = *reinterpret_cast<__half2*>(&l1);
}

// ---------------- all 4 weights -> packed single fp16 ------------------------
__global__ void split4_w(const float4* __restrict__ w0, const float4* __restrict__ w1,
                         const float4* __restrict__ w2, const float4* __restrict__ w3,
                         __half2* __restrict__ w)
{
    const int n4each = (Dm * Dm) / 4;     // 2^20
    int idx = blockIdx.x * blockDim.x + threadIdx.x;
    int t = idx >> 20;
    int r = idx & (n4each - 1);
    const float4* s = (t == 0) ? w0 : (t == 1) ? w1 : (t == 2) ? w2 : w3;
    float4 v = s[r];
    w[2*(size_t)idx]   = __floats2half2_rn(v.x, v.y);
    w[2*(size_t)idx+1] = __floats2half2_rn(v.z, v.w);
}

// ============== shared GEMM mainloop (fp16x2, 3-stage cp.async) ==============
// tiles per stage: Ahi, Alo, W(single) -> 48 KB/stage
#define KC 64
#define TILE_B 16384
#define STAGE_B (3*TILE_B)
#define GEMM_SMEM (1024 + 3*STAGE_B)

#define ISSUE_CHUNK(cc) do {                                                   \
    uint32_t sbase = su + ((cc) % 3) * STAGE_B;                                \
    const size_t kb = (size_t)(cc) * (KC * 2);                                 \
    _Pragma("unroll")                                                          \
    for (int t = 0; t < 3; t++) {                                              \
        const char* g = srcs[t] + kb;                                          \
        uint32_t s = sbase + t * TILE_B;                                       \
        _Pragma("unroll")                                                      \
        for (int i = 0; i < 4; i++) {                                          \
            int u = tid + (i << 8);                                            \
            int r = u >> 3;                                                    \
            int cb = (u & 7) << 4;                                             \
            uint32_t off = ((r >> 3) << 10) + ((r & 7) << 7) + (cb ^ ((r & 7) << 4)); \
            cp_async16(s + off, g + (size_t)r * rstride + cb);                 \
        }                                                                      \
    }                                                                          \
    CP_COMMIT();                                                               \
} while (0)

#define GEMM_MAINLOOP()                                                        \
    uint32_t aoff[4], ar7[4];                                                  \
    _Pragma("unroll")                                                          \
    for (int m = 0; m < 4; m++) {                                              \
        int r = wm*64 + m*16 + (lane & 15);                                    \
        aoff[m] = ((r >> 3) << 10) + ((r & 7) << 7);                           \
        ar7[m]  = r & 7;                                                       \
    }                                                                          \
    uint32_t boff[4], br7[4];                                                  \
    _Pragma("unroll")                                                          \
    for (int n = 0; n < 4; n++) {                                              \
        int r = wn*32 + n*8 + (lane & 7);                                      \
        boff[n] = ((r >> 3) << 10) + ((r & 7) << 7);                           \
        br7[n]  = r & 7;                                                       \
    }                                                                          \
    const uint32_t uA_lo = lane >> 4;                                          \
    const uint32_t uB_lo = lane >> 3;                                          \
    float acc[4][4][4];                                                        \
    _Pragma("unroll")                                                          \
    for (int m = 0; m < 4; m++)                                                \
        _Pragma("unroll")                                                      \
        for (int n = 0; n < 4; n++)                                            \
            _Pragma("unroll")                                                  \
            for (int q = 0; q < 4; q++) acc[m][n][q] = 0.f;                    \
    const int NCH = Ko / KC;                                                   \
    ISSUE_CHUNK(0);                                                            \
    ISSUE_CHUNK(1);                                                            \
    for (int c = 0; c < NCH; c++) {                                            \
        if (c < NCH - 1) { CP_WAIT1(); } else { CP_WAIT0(); }                  \
        __syncthreads();                                                       \
        if (c + 2 < NCH) ISSUE_CHUNK(c + 2);                                   \
        const uint32_t st  = su + (c % 3) * STAGE_B;                           \
        const uint32_t SAh = st;                                               \
        const uint32_t SAl = st + TILE_B;                                      \
        const uint32_t SB  = st + 2 * TILE_B;                                  \
        _Pragma("unroll")                                                      \
        for (int kp = 0; kp < 2; kp++) {                                       \
            uint32_t bb[4][4];                                                 \
            _Pragma("unroll")                                                  \
            for (int n = 0; n < 4; n++) {                                      \
                uint32_t uB = 4*kp + uB_lo;                                    \
                ldsm4(bb[n], SB + boff[n] + ((uB ^ br7[n]) << 4));             \
            }                                                                  \
            _Pragma("unroll")                                                  \
            for (int ki = 0; ki < 2; ki++) {                                   \
                uint32_t uA = 2*(2*kp + ki) + uA_lo;                           \
                uint32_t ah[4][4], al[4][4];                                   \
                _Pragma("unroll")                                              \
                for (int m = 0; m < 4; m++) {                                  \
                    ldsm4(ah[m], SAh + aoff[m] + ((uA ^ ar7[m]) << 4));        \
                    ldsm4(al[m], SAl + aoff[m] + ((uA ^ ar7[m]) << 4));        \
                }                                                              \
                _Pragma("unroll")                                              \
                for (int m = 0; m < 4; m++)                                    \
                    _Pragma("unroll")                                          \
                    for (int n = 0; n < 4; n++) {                              \
                        mma16816(acc[m][n], ah[m], bb[n][2*ki], bb[n][2*ki+1]); \
                        mma16816(acc[m][n], al[m], bb[n][2*ki], bb[n][2*ki+1]); \
                    }                                                          \
            }                                                                  \
        }                                                                      \
        __syncthreads();                                                       \
    }

// ---------------- fused QKV GEMM + RoPE + fp16 split epilogue ----------------
// grid (16, 32, 3): z=0 Q (rope+scale, hi/lo), z=1 K (rope, single), z=2 V (single)
__global__ void __launch_bounds__(256, 1)
gemm_qkv(const __half* __restrict__ Ahi, const __half* __restrict__ Alo,
         const __half* __restrict__ W_all, const int* __restrict__ pos,
         __half* __restrict__ Qh, __half* __restrict__ Ql,
         __half* __restrict__ Kd, __half* __restrict__ Vd)
{
    extern __shared__ char smraw[];
    char* smal = (char*)(((uintptr_t)smraw + 1023) & ~(uintptr_t)1023);
    const uint32_t su = smem_u32(smal);

    const int tid = threadIdx.x;
    const int lane = tid & 31, wid = tid >> 5;
    const int row0 = blockIdx.y << 7;
    const int col0 = blockIdx.x << 7;
    const int z = blockIdx.z;
    const int wm = wid >> 2, wn = wid & 3;
    const int Ko = Dm;

    const char* srcs[3];
    srcs[0] = (const char*)(Ahi + (size_t)row0 * Ko);
    srcs[1] = (const char*)(Alo + (size_t)row0 * Ko);
    srcs[2] = (const char*)(W_all + (size_t)z * Dm * Dm + (size_t)col0 * Ko);
    const size_t rstride = (size_t)Ko * 2;

    GEMM_MAINLOOP();

    if (z == 2) {
        // V: single fp16
#pragma unroll
        for (int m = 0; m < 4; m++) {
            int rw = row0 + wm*64 + m*16 + (lane >> 2);
#pragma unroll
            for (int n = 0; n < 4; n++) {
                int cw = col0 + wn*32 + n*8 + ((lane & 3) << 1);
                *(uint32_t*)(Vd + (size_t)rw * Dm + cw)     = pack_hi2h(acc[m][n][0], acc[m][n][1]);
                *(uint32_t*)(Vd + (size_t)(rw+8) * Dm + cw) = pack_hi2h(acc[m][n][2], acc[m][n][3]);
            }
        }
    } else if (z == 1) {
        // K: RoPE then single fp16
#pragma unroll
        for (int m = 0; m < 4; m++) {
            int rw = row0 + wm*64 + m*16 + (lane >> 2);
            float p0 = (float)pos[rw];
            float p1 = (float)pos[rw + 8];
#pragma unroll
            for (int n = 0; n < 4; n++) {
                int cw = col0 + wn*32 + n*8 + ((lane & 3) << 1);
                float inv = g_invf[(cw & 127) >> 1];
                float s0, c0, s1, c1;
                sincosf(p0 * inv, &s0, &c0);
                sincosf(p1 * inv, &s1, &c1);
                float e = acc[m][n][0], o = acc[m][n][1];
                *(uint32_t*)(Kd + (size_t)rw * Dm + cw) = pack_hi2h(e*c0 - o*s0, e*s0 + o*c0);
                e = acc[m][n][2]; o = acc[m][n][3];
                *(uint32_t*)(Kd + (size_t)(rw+8) * Dm + cw) = pack_hi2h(e*c1 - o*s1, e*s1 + o*c1);
            }
        }
    } else {
        // Q: RoPE + scale then fp16 hi/lo
#pragma unroll
        for (int m = 0; m < 4; m++) {
            int rw = row0 + wm*64 + m*16 + (lane >> 2);
            float p0 = (float)pos[rw];
            float p1 = (float)pos[rw + 8];
#pragma unroll
            for (int n = 0; n < 4; n++) {
                int cw = col0 + wn*32 + n*8 + ((lane & 3) << 1);
                float inv = g_invf[(cw & 127) >> 1];
                float s0, c0, s1, c1;
                sincosf(p0 * inv, &s0, &c0);
                sincosf(p1 * inv, &s1, &c1);
                float e = acc[m][n][0], o = acc[m][n][1];
                float re = (e*c0 - o*s0) * SCALE_C, ro = (e*s0 + o*c0) * SCALE_C;
                *(uint32_t*)(Qh + (size_t)rw * Dm + cw) = pack_hi2h(re, ro);
                *(uint32_t*)(Ql + (size_t)rw * Dm + cw) = pack_lo2h(re, ro);
                e = acc[m][n][2]; o = acc[m][n][3];
                re = (e*c1 - o*s1) * SCALE_C; ro = (e*s1 + o*c1) * SCALE_C;
                *(uint32_t*)(Qh + (size_t)(rw+8) * Dm + cw) = pack_hi2h(re, ro);
                *(uint32_t*)(Ql + (size_t)(rw+8) * Dm + cw) = pack_lo2h(re, ro);
            }
        }
    }
}

// ---------------- fp16x2 GEMM (fp32 out) for the Wo projection ---------------
__global__ void __launch_bounds__(256, 1)
gemm_out(const __half* __restrict__ Ahi, const __half* __restrict__ Alo,
         const __half* __restrict__ Bw, float* __restrict__ C, int Ko, int No)
{
    extern __shared__ char smraw[];
    char* smal = (char*)(((uintptr_t)smraw + 1023) & ~(uintptr_t)1023);
    const uint32_t su = smem_u32(smal);

    const int tid = threadIdx.x;
    const int lane = tid & 31, wid = tid >> 5;
    const int row0 = blockIdx.y << 7;
    const int col0 = blockIdx.x << 7;
    const int wm = wid >> 2, wn = wid & 3;

    const char* srcs[3];
    srcs[0] = (const char*)(Ahi + (size_t)row0 * Ko);
    srcs[1] = (const char*)(Alo + (size_t)row0 * Ko);
    srcs[2] = (const char*)(Bw + (size_t)col0 * Ko);
    const size_t rstride = (size_t)Ko * 2;

    GEMM_MAINLOOP();

#pragma unroll
    for (int m = 0; m < 4; m++) {
        int rw = row0 + wm*64 + m*16 + (lane >> 2);
#pragma unroll
        for (int n = 0; n < 4; n++) {
            int cw = col0 + wn*32 + n*8 + ((lane & 3) << 1);
            *(float2*)(C + (size_t)rw * No + cw) =
                make_float2(acc[m][n][0], acc[m][n][1]);
            *(float2*)(C + (size_t)(rw + 8) * No + cw) =
                make_float2(acc[m][n][2], acc[m][n][3]);
        }
    }
}

// ---------------- tensor-core causal flash attention (fp16x2) ----------------
// SMEM: Qhi,Qlo,K,V tiles 64x128 fp16 (256B rows, XOR swizzle) = 64 KB
#define ATT_SMEM 65536

__global__ void __launch_bounds__(128, 3)
attn_mma(const __half* __restrict__ Qh_g, const __half* __restrict__ Ql_g,
         const __half* __restrict__ K_g, const __half* __restrict__ V_g,
         __half* __restrict__ Ohi, __half* __restrict__ Olo)
{
    extern __shared__ char sm[];
    const uint32_t su = smem_u32(sm);
    const uint32_t QH = 0, QL = 16384, KS = 32768, VS = 49152;

    const int tid = threadIdx.x, lane = tid & 31, wq = tid >> 5;
    const int qt = (int)(gridDim.x - 1 - blockIdx.x);
    const int h = blockIdx.y, b = blockIdx.z;
    const int qi0 = qt << 6;
    const size_t rowbase = (size_t)b * Ll;
    const int hoff = h * Dh;

#pragma unroll
    for (int i = 0; i < 8; i++) {
        int idx = tid + (i << 7);
        int r = idx >> 4, u = idx & 15;
        uint32_t so = r * 256 + ((u ^ (r & 7)) << 4);
        size_t go = (rowbase + qi0 + r) * Dm + hoff + u * 8;
        *(float4*)(sm + QH + so) = *(const float4*)(Qh_g + go);
        *(float4*)(sm + QL + so) = *(const float4*)(Ql_g + go);
    }

    float oacc[16][4];
#pragma unroll
    for (int t = 0; t < 16; t++)
#pragma unroll
        for (int q = 0; q < 4; q++) oacc[t][q] = 0.f;
    float m0 = -1e30f, m1 = -1e30f, l0 = 0.f, l1 = 0.f;

    for (int kt = 0; kt <= qt; kt++) {
        const int kj0 = kt << 6;
        __syncthreads();
#pragma unroll
        for (int i = 0; i < 8; i++) {
            int idx = tid + (i << 7);
            int r = idx >> 4, u = idx & 15;
            uint32_t so = r * 256 + ((u ^ (r & 7)) << 4);
            size_t go = (rowbase + kj0 + r) * Dm + hoff + u * 8;
            *(float4*)(sm + KS + so) = *(const float4*)(K_g + go);
            *(float4*)(sm + VS + so) = *(const float4*)(V_g + go);
        }
        __syncthreads();

        // ---- S = Q K^T (fp16x2: Qhi*K + Qlo*K)
        float sacc[8][4];
#pragma unroll
        for (int n = 0; n < 8; n++)
#pragma unroll
            for (int q = 0; q < 4; q++) sacc[n][q] = 0.f;

#pragma unroll
        for (int kg = 0; kg < 4; kg++) {
            uint32_t bk[8][4];
#pragma unroll
            for (int n = 0; n < 8; n++) {
                int r = (n << 3) + (lane & 7);
                int u = (kg << 2) + (lane >> 3);
                ldsm4(bk[n], su + KS + r * 256 + ((u ^ (r & 7)) << 4));
            }
#pragma unroll
            for (int ki = 0; ki < 2; ki++) {
                int r = (wq << 4) + (lane & 15);
                int u = ((2 * kg + ki) << 1) + (lane >> 4);
                uint32_t o = r * 256 + ((u ^ (r & 7)) << 4);
                uint32_t ah[4], al[4];
                ldsm4(ah, su + QH + o);
                ldsm4(al, su + QL + o);
#pragma unroll
                for (int n = 0; n < 8; n++) {
                    mma16816(sacc[n], ah, bk[n][2*ki], bk[n][2*ki+1]);
                    mma16816(sacc[n], al, bk[n][2*ki], bk[n][2*ki+1]);
                }
            }
        }

        if (kt == qt) {
            int r0 = (wq << 4) + (lane >> 2), r1 = r0 + 8;
            int cb = 2 * (lane & 3);
#pragma unroll
            for (int n = 0; n < 8; n++) {
                int c0 = (n << 3) + cb, c1 = c0 + 1;
                if (c0 > r0) sacc[n][0] = -1e30f;
                if (c1 > r0) sacc[n][1] = -1e30f;
                if (c0 > r1) sacc[n][2] = -1e30f;
                if (c1 > r1) sacc[n][3] = -1e30f;
            }
        }

        float mx0 = -1e30f, mx1 = -1e30f;
#pragma unroll
        for (int n = 0; n < 8; n++) {
            mx0 = fmaxf(mx0, fmaxf(sacc[n][0], sacc[n][1]));
            mx1 = fmaxf(mx1, fmaxf(sacc[n][2], sacc[n][3]));
        }
        mx0 = fmaxf(mx0, __shfl_xor_sync(0xffffffffu, mx0, 1));
        mx0 = fmaxf(mx0, __shfl_xor_sync(0xffffffffu, mx0, 2));
        mx1 = fmaxf(mx1, __shfl_xor_sync(0xffffffffu, mx1, 1));
        mx1 = fmaxf(mx1, __shfl_xor_sync(0xffffffffu, mx1, 2));
        float mn0 = fmaxf(m0, mx0), mn1 = fmaxf(m1, mx1);
        float al0 = __expf(m0 - mn0), al1 = __expf(m1 - mn1);
        float s0 = 0.f, s1 = 0.f;
#pragma unroll
        for (int n = 0; n < 8; n++) {
            sacc[n][0] = __expf(sacc[n][0] - mn0);
            sacc[n][1] = __expf(sacc[n][1] - mn0);
            sacc[n][2] = __expf(sacc[n][2] - mn1);
            sacc[n][3] = __expf(sacc[n][3] - mn1);
            s0 += sacc[n][0] + sacc[n][1];
            s1 += sacc[n][2] + sacc[n][3];
        }
        s0 += __shfl_xor_sync(0xffffffffu, s0, 1);
        s0 += __shfl_xor_sync(0xffffffffu, s0, 2);
        s1 += __shfl_xor_sync(0xffffffffu, s1, 1);
        s1 += __shfl_xor_sync(0xffffffffu, s1, 2);
        l0 = l0 * al0 + s0; l1 = l1 * al1 + s1;
        m0 = mn0; m1 = mn1;
#pragma unroll
        for (int t = 0; t < 16; t++) {
            oacc[t][0] *= al0; oacc[t][1] *= al0;
            oacc[t][2] *= al1; oacc[t][3] *= al1;
        }

        // ---- O += P V (P fp16 hi/lo in regs, V single; V^T via ldmatrix.trans)
#pragma unroll
        for (int ks = 0; ks < 4; ks++) {
            uint32_t ph[4], pl[4];
            ph[0] = pack_hi2h(sacc[2*ks][0],   sacc[2*ks][1]);
            ph[1] = pack_hi2h(sacc[2*ks][2],   sacc[2*ks][3]);
            ph[2] = pack_hi2h(sacc[2*ks+1][0], sacc[2*ks+1][1]);
            ph[3] = pack_hi2h(sacc[2*ks+1][2], sacc[2*ks+1][3]);
            pl[0] = pack_lo2h(sacc[2*ks][0],   sacc[2*ks][1]);
            pl[1] = pack_lo2h(sacc[2*ks][2],   sacc[2*ks][3]);
            pl[2] = pack_lo2h(sacc[2*ks+1][0], sacc[2*ks+1][1]);
            pl[3] = pack_lo2h(sacc[2*ks+1][2], sacc[2*ks+1][3]);
#pragma unroll
            for (int dg = 0; dg < 8; dg++) {
                int r = (ks << 4) + (lane & 15);
                int u = (dg << 1) + (lane >> 4);
                uint32_t bv[4];
                ldsm4t(bv, su + VS + r * 256 + ((u ^ (r & 7)) << 4));
                mma16816(oacc[2*dg],   ph, bv[0], bv[1]);
                mma16816(oacc[2*dg+1], ph, bv[2], bv[3]);
                mma16816(oacc[2*dg],   pl, bv[0], bv[1]);
                mma16816(oacc[2*dg+1], pl, bv[2], bv[3]);
            }
        }
    }

    float i0 = 1.f / l0, i1 = 1.f / l1;
    size_t grow0 = rowbase + qi0 + (wq << 4) + (lane >> 2);
    size_t grow1 = grow0 + 8;
    int cb = hoff + 2 * (lane & 3);
#pragma unroll
    for (int t = 0; t < 16; t++) {
        int col = cb + (t << 3);
        float a = oacc[t][0] * i0, d = oacc[t][1] * i0;
        *(uint32_t*)(Ohi + grow0 * Dm + col) = pack_hi2h(a, d);
        *(uint32_t*)(Olo + grow0 * Dm + col) = pack_lo2h(a, d);
        float e = oacc[t][2] * i1, f = oacc[t][3] * i1;
        *(uint32_t*)(Ohi + grow1 * Dm + col) = pack_hi2h(e, f);
        *(uint32_t*)(Olo + grow1 * Dm + col) = pack_lo2h(e, f);
    }
}

// ---------------- launch ------------------------------------------------------
extern "C" void kernel_launch(void* const* d_in, const int* in_sizes, int n_in,
                              void* d_out, int out_size)
{
    const float* x  = (const float*)d_in[0];
    const int*  pos = (const int*)d_in[1];
    const float* Wq = (const float*)d_in[2];
    const float* Wk = (const float*)d_in[3];
    const float* Wv = (const float*)d_in[4];
    const float* Wo = (const float*)d_in[5];
    float* out = (float*)d_out;

    __half *ahi, *alo, *w, *qhi, *qlo, *kd, *vd;
    cudaGetSymbolAddress((void**)&ahi, g_ahi);
    cudaGetSymbolAddress((void**)&alo, g_alo);
    cudaGetSymbolAddress((void**)&w,   g_w);
    cudaGetSymbolAddress((void**)&qhi, g_qhi);
    cudaGetSymbolAddress((void**)&qlo, g_qlo);
    cudaGetSymbolAddress((void**)&kd,  g_k);
    cudaGetSymbolAddress((void**)&vd,  g_v);

    invf_kernel<<<1, 64>>>();

    const int nx4 = (Mm * Dm) / 4;
    const int nw4 = (Dm * Dm) / 4;

    cudaFuncSetAttribute(gemm_qkv,
                         cudaFuncAttributeMaxDynamicSharedMemorySize, GEMM_SMEM);
    cudaFuncSetAttribute(gemm_out,
                         cudaFuncAttributeMaxDynamicSharedMemorySize, GEMM_SMEM);
    cudaFuncSetAttribute(attn_mma,
                         cudaFuncAttributeMaxDynamicSharedMemorySize, ATT_SMEM);

    // x -> fp16 hi/lo
    split_x<<<nx4/256, 256>>>((const float4*)x, (__half2*)ahi, (__half2*)alo, nx4);
    // all 4 weights -> packed single fp16
    split4_w<<<(4*nw4)/256, 256>>>((const float4*)Wq, (const float4*)Wk,
                                   (const float4*)Wv, (const float4*)Wo, (__half2*)w);

    // fused QKV GEMM + RoPE + split (one launch, 1536 CTAs)
    dim3 qkvgrid(Dm/128, Mm/128, 3);
    gemm_qkv<<<qkvgrid, 256, GEMM_SMEM>>>(ahi, alo, w, pos, qhi, qlo, kd, vd);

    // attention -> O hi/lo into g_ahi/g_alo
    dim3 agrid(Ll/64, Hn, Bb);
    attn_mma<<<agrid, 128, ATT_SMEM>>>(qhi, qlo, kd, vd, ahi, alo);

    // out = O Wo^T (fp32)
    dim3 ggrid(Dm/128, Mm/128);
    gemm_out<<<ggrid, 256, GEMM_SMEM>>>(ahi, alo, w + (size_t)3*Dm*Dm, out, Dm, Dm);
}

// round 9
// speedup vs baseline: 7.9680x; 1.0329x over previous
#include <cuda_runtime.h>
#include <cuda_fp16.h>
#include <math.h>
#include <stdint.h>

#define Dm 2048
#define Hn 16
#define Dh 128
#define Bb 2
#define Ll 2048
#define Mm (Bb*Ll)   /* 4096 rows */
#define SCALE_C 0.08838834764831845f   /* 1/sqrt(128) */

// ---------------- scratch (static device globals; no runtime allocation) ----
__device__ __half g_ahi[(size_t)Mm * Dm];   // x split hi, later O split hi
__device__ __half g_alo[(size_t)Mm * Dm];
__device__ __half g_w[(size_t)4 * Dm * Dm]; // Wq,Wk,Wv,Wo single fp16
__device__ __half g_qhi[(size_t)Mm * Dm];
__device__ __half g_qlo[(size_t)Mm * Dm];
__device__ __half g_k[(size_t)Mm * Dm];     // K single fp16 (post-rope)
__device__ __half g_v[(size_t)Mm * Dm];     // V single fp16
__device__ float g_invf[Dh/2];

// ======================= helpers =============================================
__device__ __forceinline__ uint32_t smem_u32(const void* p) {
    uint32_t a;
    asm("{ .reg .u64 t; cvta.to.shared.u64 t, %1; cvt.u32.u64 %0, t; }"
        : "=r"(a) : "l"(p));
    return a;
}
__device__ __forceinline__ void cp_async16(uint32_t saddr, const void* gaddr) {
    asm volatile("cp.async.cg.shared.global [%0], [%1], 16;"
                 :: "r"(saddr), "l"(gaddr) : "memory");
}
#define CP_COMMIT() asm volatile("cp.async.commit_group;" ::: "memory")
#define CP_WAIT1()  asm volatile("cp.async.wait_group 1;" ::: "memory")
#define CP_WAIT0()  asm volatile("cp.async.wait_group 0;" ::: "memory")

__device__ __forceinline__ void ldsm4(uint32_t* d, uint32_t a) {
    asm volatile("ldmatrix.sync.aligned.m8n8.x4.shared.b16 {%0,%1,%2,%3}, [%4];"
                 : "=r"(d[0]), "=r"(d[1]), "=r"(d[2]), "=r"(d[3]) : "r"(a));
}
__device__ __forceinline__ void ldsm4t(uint32_t* d, uint32_t a) {
    asm volatile("ldmatrix.sync.aligned.m8n8.x4.trans.shared.b16 {%0,%1,%2,%3}, [%4];"
                 : "=r"(d[0]), "=r"(d[1]), "=r"(d[2]), "=r"(d[3]) : "r"(a));
}
__device__ __forceinline__ void mma16816(float* d, const uint32_t* a,
                                         uint32_t b0, uint32_t b1) {
    asm volatile(
        "mma.sync.aligned.m16n8k16.row.col.f32.f16.f16.f32 "
        "{%0,%1,%2,%3}, {%4,%5,%6,%7}, {%8,%9}, {%0,%1,%2,%3};"
        : "+f"(d[0]), "+f"(d[1]), "+f"(d[2]), "+f"(d[3])
        : "r"(a[0]), "r"(a[1]), "r"(a[2]), "r"(a[3]), "r"(b0), "r"(b1));
}
__device__ __forceinline__ uint32_t pack_hi2h(float a, float b) {
    __half2 t = __floats2half2_rn(a, b);
    return *reinterpret_cast<uint32_t*>(&t);
}
__device__ __forceinline__ uint32_t pack_lo2h(float a, float b) {
    float ra = a - __half2float(__float2half_rn(a));
    float rb = b - __half2float(__float2half_rn(b));
    __half2 t = __floats2half2_rn(ra, rb);
    return *reinterpret_cast<uint32_t*>(&t);
}

// ---------------- inv_freq table --------------------------------------------
__global__ void invf_kernel() {
    int i = threadIdx.x;
    if (i < Dh/2)
        g_invf[i] = (float)pow(10000.0, -(double)(2*i) / (double)Dh);
}

// ---------------- fp32 -> fp16 hi/lo split (x) --------------------------------
__global__ void split_x(const float4* __restrict__ src,
                        __half2* __restrict__ hi, __half2* __restrict__ lo, int n4)
{
    int i = blockIdx.x * blockDim.x + threadIdx.x;
    if (i >= n4) return;
    float4 v = src[i];
    uint32_t h0 = pack_hi2h(v.x, v.y), h1 = pack_hi2h(v.z, v.w);
    uint32_t l0 = pack_lo2h(v.x, v.y), l1 = pack_lo2h(v.z, v.w);
    hi[2*i]   = *reinterpret_cast<__half2*>(&h0);
    hi[2*i+1] = *reinterpret_cast<__half2*>(&h1);
    lo[2*i]   = *reinterpret_cast<__half2*>(&l0);
    lo[2*i+1] = *reinterpret_cast<__half2*>(&l1);
}

// ---------------- all 4 weights -> packed single fp16 ------------------------
__global__ void split4_w(const float4* __restrict__ w0, const float4* __restrict__ w1,
                         const float4* __restrict__ w2, const float4* __restrict__ w3,
                         __half2* __restrict__ w)
{
    const int n4each = (Dm * Dm) / 4;     // 2^20
    int idx = blockIdx.x * blockDim.x + threadIdx.x;
    int t = idx >> 20;
    int r = idx & (n4each - 1);
    const float4* s = (t == 0) ? w0 : (t == 1) ? w1 : (t == 2) ? w2 : w3;
    float4 v = s[r];
    w[2*(size_t)idx]   = __floats2half2_rn(v.x, v.y);
    w[2*(size_t)idx+1] = __floats2half2_rn(v.z, v.w);
}

// ============== shared GEMM mainloop (fp16x2, 3-stage, 512 threads) ==========
// tiles per stage: Ahi, Alo, W(single) -> 48 KB/stage
// 512 threads = 16 warps, 4x4 warp grid, warp tile 32x32 (2 m-frags x 4 n-frags)
#define KC 64
#define TILE_B 16384
#define STAGE_B (3*TILE_B)
#define GEMM_SMEM (1024 + 3*STAGE_B)

#define ISSUE_CHUNK(cc) do {                                                   \
    uint32_t sbase = su + ((cc) % 3) * STAGE_B;                                \
    const size_t kb = (size_t)(cc) * (KC * 2);                                 \
    _Pragma("unroll")                                                          \
    for (int t = 0; t < 3; t++) {                                              \
        const char* g = srcs[t] + kb;                                          \
        uint32_t s = sbase + t * TILE_B;                                       \
        _Pragma("unroll")                                                      \
        for (int i = 0; i < 2; i++) {                                          \
            int u = tid + (i << 9);                                            \
            int r = u >> 3;                                                    \
            int cb = (u & 7) << 4;                                             \
            uint32_t off = ((r >> 3) << 10) + ((r & 7) << 7) + (cb ^ ((r & 7) << 4)); \
            cp_async16(s + off, g + (size_t)r * rstride + cb);                 \
        }                                                                      \
    }                                                                          \
    CP_COMMIT();                                                               \
} while (0)

#define GEMM_MAINLOOP()                                                        \
    uint32_t aoff[2], ar7[2];                                                  \
    _Pragma("unroll")                                                          \
    for (int m = 0; m < 2; m++) {                                              \
        int r = wm*32 + m*16 + (lane & 15);                                    \
        aoff[m] = ((r >> 3) << 10) + ((r & 7) << 7);                           \
        ar7[m]  = r & 7;                                                       \
    }                                                                          \
    uint32_t boff[4], br7[4];                                                  \
    _Pragma("unroll")                                                          \
    for (int n = 0; n < 4; n++) {                                              \
        int r = wn*32 + n*8 + (lane & 7);                                      \
        boff[n] = ((r >> 3) << 10) + ((r & 7) << 7);                           \
        br7[n]  = r & 7;                                                       \
    }                                                                          \
    const uint32_t uA_lo = lane >> 4;                                          \
    const uint32_t uB_lo = lane >> 3;                                          \
    float acc[2][4][4];                                                        \
    _Pragma("unroll")                                                          \
    for (int m = 0; m < 2; m++)                                                \
        _Pragma("unroll")                                                      \
        for (int n = 0; n < 4; n++)                                            \
            _Pragma("unroll")                                                  \
            for (int q = 0; q < 4; q++) acc[m][n][q] = 0.f;                    \
    const int NCH = Ko / KC;                                                   \
    ISSUE_CHUNK(0);                                                            \
    ISSUE_CHUNK(1);                                                            \
    for (int c = 0; c < NCH; c++) {                                            \
        if (c < NCH - 1) { CP_WAIT1(); } else { CP_WAIT0(); }                  \
        __syncthreads();                                                       \
        if (c + 2 < NCH) ISSUE_CHUNK(c + 2);                                   \
        const uint32_t st  = su + (c % 3) * STAGE_B;                           \
        const uint32_t SAh = st;                                               \
        const uint32_t SAl = st + TILE_B;                                      \
        const uint32_t SB  = st + 2 * TILE_B;                                  \
        _Pragma("unroll")                                                      \
        for (int kp = 0; kp < 2; kp++) {                                       \
            uint32_t bb[4][4];                                                 \
            _Pragma("unroll")                                                  \
            for (int n = 0; n < 4; n++) {                                      \
                uint32_t uB = 4*kp + uB_lo;                                    \
                ldsm4(bb[n], SB + boff[n] + ((uB ^ br7[n]) << 4));             \
            }                                                                  \
            _Pragma("unroll")                                                  \
            for (int ki = 0; ki < 2; ki++) {                                   \
                uint32_t uA = 2*(2*kp + ki) + uA_lo;                           \
                uint32_t ah[2][4], al[2][4];                                   \
                _Pragma("unroll")                                              \
                for (int m = 0; m < 2; m++) {                                  \
                    ldsm4(ah[m], SAh + aoff[m] + ((uA ^ ar7[m]) << 4));        \
                    ldsm4(al[m], SAl + aoff[m] + ((uA ^ ar7[m]) << 4));        \
                }                                                              \
                _Pragma("unroll")                                              \
                for (int m = 0; m < 2; m++)                                    \
                    _Pragma("unroll")                                          \
                    for (int n = 0; n < 4; n++) {                              \
                        mma16816(acc[m][n], ah[m], bb[n][2*ki], bb[n][2*ki+1]); \
                        mma16816(acc[m][n], al[m], bb[n][2*ki], bb[n][2*ki+1]); \
                    }                                                          \
            }                                                                  \
        }                                                                      \
    }

// ---------------- fused QKV GEMM + RoPE + fp16 split epilogue ----------------
// grid (16, 32, 3): z=0 Q (rope+scale, hi/lo), z=1 K (rope, single), z=2 V (single)
__global__ void __launch_bounds__(512, 1)
gemm_qkv(const __half* __restrict__ Ahi, const __half* __restrict__ Alo,
         const __half* __restrict__ W_all, const int* __restrict__ pos,
         __half* __restrict__ Qh, __half* __restrict__ Ql,
         __half* __restrict__ Kd, __half* __restrict__ Vd)
{
    extern __shared__ char smraw[];
    char* smal = (char*)(((uintptr_t)smraw + 1023) & ~(uintptr_t)1023);
    const uint32_t su = smem_u32(smal);

    const int tid = threadIdx.x;
    const int lane = tid & 31, wid = tid >> 5;
    const int row0 = blockIdx.y << 7;
    const int col0 = blockIdx.x << 7;
    const int z = blockIdx.z;
    const int wm = wid >> 2, wn = wid & 3;
    const int Ko = Dm;

    const char* srcs[3];
    srcs[0] = (const char*)(Ahi + (size_t)row0 * Ko);
    srcs[1] = (const char*)(Alo + (size_t)row0 * Ko);
    srcs[2] = (const char*)(W_all + (size_t)z * Dm * Dm + (size_t)col0 * Ko);
    const size_t rstride = (size_t)Ko * 2;

    GEMM_MAINLOOP();

    if (z == 2) {
        // V: single fp16
#pragma unroll
        for (int m = 0; m < 2; m++) {
            int rw = row0 + wm*32 + m*16 + (lane >> 2);
#pragma unroll
            for (int n = 0; n < 4; n++) {
                int cw = col0 + wn*32 + n*8 + ((lane & 3) << 1);
                *(uint32_t*)(Vd + (size_t)rw * Dm + cw)     = pack_hi2h(acc[m][n][0], acc[m][n][1]);
                *(uint32_t*)(Vd + (size_t)(rw+8) * Dm + cw) = pack_hi2h(acc[m][n][2], acc[m][n][3]);
            }
        }
    } else if (z == 1) {
        // K: RoPE then single fp16
#pragma unroll
        for (int m = 0; m < 2; m++) {
            int rw = row0 + wm*32 + m*16 + (lane >> 2);
            float p0 = (float)pos[rw];
            float p1 = (float)pos[rw + 8];
#pragma unroll
            for (int n = 0; n < 4; n++) {
                int cw = col0 + wn*32 + n*8 + ((lane & 3) << 1);
                float inv = g_invf[(cw & 127) >> 1];
                float s0, c0, s1, c1;
                sincosf(p0 * inv, &s0, &c0);
                sincosf(p1 * inv, &s1, &c1);
                float e = acc[m][n][0], o = acc[m][n][1];
                *(uint32_t*)(Kd + (size_t)rw * Dm + cw) = pack_hi2h(e*c0 - o*s0, e*s0 + o*c0);
                e = acc[m][n][2]; o = acc[m][n][3];
                *(uint32_t*)(Kd + (size_t)(rw+8) * Dm + cw) = pack_hi2h(e*c1 - o*s1, e*s1 + o*c1);
            }
        }
    } else {
        // Q: RoPE + scale then fp16 hi/lo
#pragma unroll
        for (int m = 0; m < 2; m++) {
            int rw = row0 + wm*32 + m*16 + (lane >> 2);
            float p0 = (float)pos[rw];
            float p1 = (float)pos[rw + 8];
#pragma unroll
            for (int n = 0; n < 4; n++) {
                int cw = col0 + wn*32 + n*8 + ((lane & 3) << 1);
                float inv = g_invf[(cw & 127) >> 1];
                float s0, c0, s1, c1;
                sincosf(p0 * inv, &s0, &c0);
                sincosf(p1 * inv, &s1, &c1);
                float e = acc[m][n][0], o = acc[m][n][1];
                float re = (e*c0 - o*s0) * SCALE_C, ro = (e*s0 + o*c0) * SCALE_C;
                *(uint32_t*)(Qh + (size_t)rw * Dm + cw) = pack_hi2h(re, ro);
                *(uint32_t*)(Ql + (size_t)rw * Dm + cw) = pack_lo2h(re, ro);
                e = acc[m][n][2]; o = acc[m][n][3];
                re = (e*c1 - o*s1) * SCALE_C; ro = (e*s1 + o*c1) * SCALE_C;
                *(uint32_t*)(Qh + (size_t)(rw+8) * Dm + cw) = pack_hi2h(re, ro);
                *(uint32_t*)(Ql + (size_t)(rw+8) * Dm + cw) = pack_lo2h(re, ro);
            }
        }
    }
}

// ---------------- fp16x2 GEMM (fp32 out) for the Wo projection ---------------
__global__ void __launch_bounds__(512, 1)
gemm_out(const __half* __restrict__ Ahi, const __half* __restrict__ Alo,
         const __half* __restrict__ Bw, float* __restrict__ C, int Ko, int No)
{
    extern __shared__ char smraw[];
    char* smal = (char*)(((uintptr_t)smraw + 1023) & ~(uintptr_t)1023);
    const uint32_t su = smem_u32(smal);

    const int tid = threadIdx.x;
    const int lane = tid & 31, wid = tid >> 5;
    const int row0 = blockIdx.y << 7;
    const int col0 = blockIdx.x << 7;
    const int wm = wid >> 2, wn = wid & 3;

    const char* srcs[3];
    srcs[0] = (const char*)(Ahi + (size_t)row0 * Ko);
    srcs[1] = (const char*)(Alo + (size_t)row0 * Ko);
    srcs[2] = (const char*)(Bw + (size_t)col0 * Ko);
    const size_t rstride = (size_t)Ko * 2;

    GEMM_MAINLOOP();

#pragma unroll
    for (int m = 0; m < 2; m++) {
        int rw = row0 + wm*32 + m*16 + (lane >> 2);
#pragma unroll
        for (int n = 0; n < 4; n++) {
            int cw = col0 + wn*32 + n*8 + ((lane & 3) << 1);
            *(float2*)(C + (size_t)rw * No + cw) =
                make_float2(acc[m][n][0], acc[m][n][1]);
            *(float2*)(C + (size_t)(rw + 8) * No + cw) =
                make_float2(acc[m][n][2], acc[m][n][3]);
        }
    }
}

// ---------------- tensor-core causal flash attention (fp16x2) ----------------
// SMEM: Qhi,Qlo,K,V tiles 64x128 fp16 (256B rows, XOR swizzle) = 64 KB
#define ATT_SMEM 65536

__global__ void __launch_bounds__(128, 3)
attn_mma(const __half* __restrict__ Qh_g, const __half* __restrict__ Ql_g,
         const __half* __restrict__ K_g, const __half* __restrict__ V_g,
         __half* __restrict__ Ohi, __half* __restrict__ Olo)
{
    extern __shared__ char sm[];
    const uint32_t su = smem_u32(sm);
    const uint32_t QH = 0, QL = 16384, KS = 32768, VS = 49152;

    const int tid = threadIdx.x, lane = tid & 31, wq = tid >> 5;
    const int qt = (int)(gridDim.x - 1 - blockIdx.x);
    const int h = blockIdx.y, b = blockIdx.z;
    const int qi0 = qt << 6;
    const size_t rowbase = (size_t)b * Ll;
    const int hoff = h * Dh;

#pragma unroll
    for (int i = 0; i < 8; i++) {
        int idx = tid + (i << 7);
        int r = idx >> 4, u = idx & 15;
        uint32_t so = r * 256 + ((u ^ (r & 7)) << 4);
        size_t go = (rowbase + qi0 + r) * Dm + hoff + u * 8;
        *(float4*)(sm + QH + so) = *(const float4*)(Qh_g + go);
        *(float4*)(sm + QL + so) = *(const float4*)(Ql_g + go);
    }

    float oacc[16][4];
#pragma unroll
    for (int t = 0; t < 16; t++)
#pragma unroll
        for (int q = 0; q < 4; q++) oacc[t][q] = 0.f;
    float m0 = -1e30f, m1 = -1e30f, l0 = 0.f, l1 = 0.f;

    for (int kt = 0; kt <= qt; kt++) {
        const int kj0 = kt << 6;
        __syncthreads();
#pragma unroll
        for (int i = 0; i < 8; i++) {
            int idx = tid + (i << 7);
            int r = idx >> 4, u = idx & 15;
            uint32_t so = r * 256 + ((u ^ (r & 7)) << 4);
            size_t go = (rowbase + kj0 + r) * Dm + hoff + u * 8;
            *(float4*)(sm + KS + so) = *(const float4*)(K_g + go);
            *(float4*)(sm + VS + so) = *(const float4*)(V_g + go);
        }
        __syncthreads();

        // ---- S = Q K^T (fp16x2: Qhi*K + Qlo*K)
        float sacc[8][4];
#pragma unroll
        for (int n = 0; n < 8; n++)
#pragma unroll
            for (int q = 0; q < 4; q++) sacc[n][q] = 0.f;

#pragma unroll
        for (int kg = 0; kg < 4; kg++) {
            uint32_t bk[8][4];
#pragma unroll
            for (int n = 0; n < 8; n++) {
                int r = (n << 3) + (lane & 7);
                int u = (kg << 2) + (lane >> 3);
                ldsm4(bk[n], su + KS + r * 256 + ((u ^ (r & 7)) << 4));
            }
#pragma unroll
            for (int ki = 0; ki < 2; ki++) {
                int r = (wq << 4) + (lane & 15);
                int u = ((2 * kg + ki) << 1) + (lane >> 4);
                uint32_t o = r * 256 + ((u ^ (r & 7)) << 4);
                uint32_t ah[4], al[4];
                ldsm4(ah, su + QH + o);
                ldsm4(al, su + QL + o);
#pragma unroll
                for (int n = 0; n < 8; n++) {
                    mma16816(sacc[n], ah, bk[n][2*ki], bk[n][2*ki+1]);
                    mma16816(sacc[n], al, bk[n][2*ki], bk[n][2*ki+1]);
                }
            }
        }

        if (kt == qt) {
            int r0 = (wq << 4) + (lane >> 2), r1 = r0 + 8;
            int cb = 2 * (lane & 3);
#pragma unroll
            for (int n = 0; n < 8; n++) {
                int c0 = (n << 3) + cb, c1 = c0 + 1;
                if (c0 > r0) sacc[n][0] = -1e30f;
                if (c1 > r0) sacc[n][1] = -1e30f;
                if (c0 > r1) sacc[n][2] = -1e30f;
                if (c1 > r1) sacc[n][3] = -1e30f;
            }
        }

        float mx0 = -1e30f, mx1 = -1e30f;
#pragma unroll
        for (int n = 0; n < 8; n++) {
            mx0 = fmaxf(mx0, fmaxf(sacc[n][0], sacc[n][1]));
            mx1 = fmaxf(mx1, fmaxf(sacc[n][2], sacc[n][3]));
        }
        mx0 = fmaxf(mx0, __shfl_xor_sync(0xffffffffu, mx0, 1));
        mx0 = fmaxf(mx0, __shfl_xor_sync(0xffffffffu, mx0, 2));
        mx1 = fmaxf(mx1, __shfl_xor_sync(0xffffffffu, mx1, 1));
        mx1 = fmaxf(mx1, __shfl_xor_sync(0xffffffffu, mx1, 2));
        float mn0 = fmaxf(m0, mx0), mn1 = fmaxf(m1, mx1);
        float al0 = __expf(m0 - mn0), al1 = __expf(m1 - mn1);
        float s0 = 0.f, s1 = 0.f;
#pragma unroll
        for (int n = 0; n < 8; n++) {
            sacc[n][0] = __expf(sacc[n][0] - mn0);
            sacc[n][1] = __expf(sacc[n][1] - mn0);
            sacc[n][2] = __expf(sacc[n][2] - mn1);
            sacc[n][3] = __expf(sacc[n][3] - mn1);
            s0 += sacc[n][0] + sacc[n][1];
            s1 += sacc[n][2] + sacc[n][3];
        }
        s0 += __shfl_xor_sync(0xffffffffu, s0, 1);
        s0 += __shfl_xor_sync(0xffffffffu, s0, 2);
        s1 += __shfl_xor_sync(0xffffffffu, s1, 1);
        s1 += __shfl_xor_sync(0xffffffffu, s1, 2);
        l0 = l0 * al0 + s0; l1 = l1 * al1 + s1;
        m0 = mn0; m1 = mn1;
#pragma unroll
        for (int t = 0; t < 16; t++) {
            oacc[t][0] *= al0; oacc[t][1] *= al0;
            oacc[t][2] *= al1; oacc[t][3] *= al1;
        }

        // ---- O += P V (P fp16 hi/lo in regs, V single; V^T via ldmatrix.trans)
#pragma unroll
        for (int ks = 0; ks < 4; ks++) {
            uint32_t ph[4], pl[4];
            ph[0] = pack_hi2h(sacc[2*ks][0],   sacc[2*ks][1]);
            ph[1] = pack_hi2h(sacc[2*ks][2],   sacc[2*ks][3]);
            ph[2] = pack_hi2h(sacc[2*ks+1][0], sacc[2*ks+1][1]);
            ph[3] = pack_hi2h(sacc[2*ks+1][2], sacc[2*ks+1][3]);
            pl[0] = pack_lo2h(sacc[2*ks][0],   sacc[2*ks][1]);
            pl[1] = pack_lo2h(sacc[2*ks][2],   sacc[2*ks][3]);
            pl[2] = pack_lo2h(sacc[2*ks+1][0], sacc[2*ks+1][1]);
            pl[3] = pack_lo2h(sacc[2*ks+1][2], sacc[2*ks+1][3]);
#pragma unroll
            for (int dg = 0; dg < 8; dg++) {
                int r = (ks << 4) + (lane & 15);
                int u = (dg << 1) + (lane >> 4);
                uint32_t bv[4];
                ldsm4t(bv, su + VS + r * 256 + ((u ^ (r & 7)) << 4));
                mma16816(oacc[2*dg],   ph, bv[0], bv[1]);
                mma16816(oacc[2*dg+1], ph, bv[2], bv[3]);
                mma16816(oacc[2*dg],   pl, bv[0], bv[1]);
                mma16816(oacc[2*dg+1], pl, bv[2], bv[3]);
            }
        }
    }

    float i0 = 1.f / l0, i1 = 1.f / l1;
    size_t grow0 = rowbase + qi0 + (wq << 4) + (lane >> 2);
    size_t grow1 = grow0 + 8;
    int cb = hoff + 2 * (lane & 3);
#pragma unroll
    for (int t = 0; t < 16; t++) {
        int col = cb + (t << 3);
        float a = oacc[t][0] * i0, d = oacc[t][1] * i0;
        *(uint32_t*)(Ohi + grow0 * Dm + col) = pack_hi2h(a, d);
        *(uint32_t*)(Olo + grow0 * Dm + col) = pack_lo2h(a, d);
        float e = oacc[t][2] * i1, f = oacc[t][3] * i1;
        *(uint32_t*)(Ohi + grow1 * Dm + col) = pack_hi2h(e, f);
        *(uint32_t*)(Olo + grow1 * Dm + col) = pack_lo2h(e, f);
    }
}

// ---------------- launch ------------------------------------------------------
extern "C" void kernel_launch(void* const* d_in, const int* in_sizes, int n_in,
                              void* d_out, int out_size)
{
    const float* x  = (const float*)d_in[0];
    const int*  pos = (const int*)d_in[1];
    const float* Wq = (const float*)d_in[2];
    const float* Wk = (const float*)d_in[3];
    const float* Wv = (const float*)d_in[4];
    const float* Wo = (const float*)d_in[5];
    float* out = (float*)d_out;

    __half *ahi, *alo, *w, *qhi, *qlo, *kd, *vd;
    cudaGetSymbolAddress((void**)&ahi, g_ahi);
    cudaGetSymbolAddress((void**)&alo, g_alo);
    cudaGetSymbolAddress((void**)&w,   g_w);
    cudaGetSymbolAddress((void**)&qhi, g_qhi);
    cudaGetSymbolAddress((void**)&qlo, g_qlo);
    cudaGetSymbolAddress((void**)&kd,  g_k);
    cudaGetSymbolAddress((void**)&vd,  g_v);

    invf_kernel<<<1, 64>>>();

    const int nx4 = (Mm * Dm) / 4;
    const int nw4 = (Dm * Dm) / 4;

    cudaFuncSetAttribute(gemm_qkv,
                         cudaFuncAttributeMaxDynamicSharedMemorySize, GEMM_SMEM);
    cudaFuncSetAttribute(gemm_out,
                         cudaFuncAttributeMaxDynamicSharedMemorySize, GEMM_SMEM);
    cudaFuncSetAttribute(attn_mma,
                         cudaFuncAttributeMaxDynamicSharedMemorySize, ATT_SMEM);

    // x -> fp16 hi/lo
    split_x<<<nx4/256, 256>>>((const float4*)x, (__half2*)ahi, (__half2*)alo, nx4);
    // all 4 weights -> packed single fp16
    split4_w<<<(4*nw4)/256, 256>>>((const float4*)Wq, (const float4*)Wk,
                                   (const float4*)Wv, (const float4*)Wo, (__half2*)w);

    // fused QKV GEMM + RoPE + split (one launch, 1536 CTAs, 512 thr)
    dim3 qkvgrid(Dm/128, Mm/128, 3);
    gemm_qkv<<<qkvgrid, 512, GEMM_SMEM>>>(ahi, alo, w, pos, qhi, qlo, kd, vd);

    // attention -> O hi/lo into g_ahi/g_alo
    dim3 agrid(Ll/64, Hn, Bb);
    attn_mma<<<agrid, 128, ATT_SMEM>>>(qhi, qlo, kd, vd, ahi, alo);

    // out = O Wo^T (fp32)
    dim3 ggrid(Dm/128, Mm/128);
    gemm_out<<<ggrid, 512, GEMM_SMEM>>>(ahi, alo, w + (size_t)3*Dm*Dm, out, Dm, Dm);
}